// round 8
// baseline (speedup 1.0000x reference)
#include <cuda_runtime.h>
#include <cuda_fp16.h>
#include <math.h>
#include <stdint.h>

// ---------------- scratch ----------------
#define NROWS 8192
#define DV    512
__device__ float  g_Qp [NROWS * DV];          // Q projected, fp32 (residual + frag source)
__device__ __half g_Kph[NROWS * DV];          // K projected, half, [row][512]
__device__ __half g_Vth[NROWS * DV];          // V projected, half, transposed [b][h][d][key]
__device__ float  g_O  [NROWS * DV];
__device__ float  g_X  [NROWS * DV];
__device__ __half g_Xh [NROWS * DV];
__device__ float  g_T  [NROWS * DV];
__device__ __half g_Qh [NROWS * DV];          // raw Q in half
__device__ __half g_Kh [NROWS * DV];          // raw K in half
__device__ __half g_Wh [4 * DV * DV];         // Wq,Wk,Wv,Wo in half

// ---------------- helpers ----------------
__device__ __forceinline__ unsigned packh2(float lo, float hi) {
    __half2 h = __floats2half2_rn(lo, hi);
    return *reinterpret_cast<unsigned*>(&h);
}
__device__ __forceinline__ void mmah16(float* d, const unsigned* a, const unsigned* b) {
    asm volatile(
        "mma.sync.aligned.m16n8k16.row.col.f32.f16.f16.f32 "
        "{%0,%1,%2,%3},{%4,%5,%6,%7},{%8,%9},{%0,%1,%2,%3};"
        : "+f"(d[0]), "+f"(d[1]), "+f"(d[2]), "+f"(d[3])
        : "r"(a[0]), "r"(a[1]), "r"(a[2]), "r"(a[3]), "r"(b[0]), "r"(b[1]));
}
__device__ __forceinline__ void ldsm4(unsigned& r0, unsigned& r1, unsigned& r2, unsigned& r3,
                                      uint32_t addr) {
    asm volatile("ldmatrix.sync.aligned.m8n8.x4.shared.b16 {%0,%1,%2,%3}, [%4];"
                 : "=r"(r0), "=r"(r1), "=r"(r2), "=r"(r3) : "r"(addr));
}
__device__ __forceinline__ void cpa16(uint32_t s, const void* g) {
    asm volatile("cp.async.cg.shared.global [%0], [%1], 16;" :: "r"(s), "l"(g));
}
#define CPA_COMMIT() asm volatile("cp.async.commit_group;")
#define CPA_WAIT(n)  asm volatile("cp.async.wait_group %0;" :: "n"(n))

// ---------------- fp32 -> half batched convert ----------------
struct CArgs { const float* src[6]; __half* dst[6]; int n[6]; };
__global__ __launch_bounds__(256) void conv_half(CArgs a) {
    const int z = blockIdx.y;
    const int i = (blockIdx.x * 256 + threadIdx.x) * 8;
    if (i >= a.n[z]) return;
    const float4 f0 = *(const float4*)(a.src[z] + i);
    const float4 f1 = *(const float4*)(a.src[z] + i + 4);
    __half2 h[4];
    h[0] = __floats2half2_rn(f0.x, f0.y);
    h[1] = __floats2half2_rn(f0.z, f0.w);
    h[2] = __floats2half2_rn(f1.x, f1.y);
    h[3] = __floats2half2_rn(f1.z, f1.w);
    *(uint4*)(a.dst[z] + i) = *(uint4*)h;
}

// ---------------- f16 GEMM core: 3-stage cp.async + ldmatrix b16 ----------------
// C = A[8192,512] @ W[512,512]^T + bias.
// mode 0: fp32 store; 1: relu + residual(resid) fp32 store; 2: half transposed (Vt);
// 3: half store [row][512].
#define GH 40                         // halves per row (80 B: 16B-aligned, quad-distinct)
#define GSTGH (2 * 128 * GH)          // halves per stage (A then B)
#define GEMM_SMEM (3 * GSTGH * 2)     // 61440 B

__device__ __forceinline__ void gemm_core(const __half* __restrict__ A,
                                          const __half* __restrict__ W,
                                          const float* __restrict__ bias,
                                          const float* __restrict__ resid,
                                          void* Cv, int mode, __half* gsm)
{
    const int tid  = threadIdx.x;
    const int lane = tid & 31;
    const int warp = tid >> 5;
    const int wm = warp & 3;
    const int wn = warp >> 2;
    const int bm = blockIdx.y * 128;
    const int bn = blockIdx.x * 128;
    const int g4 = lane >> 2;
    const int t4 = lane & 3;
    const int i8 = lane & 7;
    const int K = 512, N = 512;

    const uint32_t gsu = (uint32_t)__cvta_generic_to_shared(gsm);
    // A frags: bit3 -> row-half, bit4 -> k-half  => x4 order (r0k0,r8k0,r0k8,r8k8)
    const uint32_t obA = (uint32_t)(((wm * 32 + ((lane >> 3) & 1) * 8 + i8) * GH
                                     + (lane >> 4) * 8) * 2);
    // B frags: bit4 -> n-half, bit3 -> k-half    => x4 order (n0k0,n0k8,n8k0,n8k8)
    const uint32_t obB = (uint32_t)(128 * GH * 2
                       + ((wn * 64 + ((lane >> 4) & 1) * 8 + i8) * GH
                          + ((lane >> 3) & 1) * 8) * 2);

    float acc[2][8][4];
#pragma unroll
    for (int mi = 0; mi < 2; mi++)
#pragma unroll
        for (int ni = 0; ni < 8; ni++)
#pragma unroll
            for (int j = 0; j < 4; j++) acc[mi][ni][j] = 0.f;

    auto issue = [&](int it) {
        __half* Adst = gsm + (it % 3) * GSTGH;
        __half* Bdst = Adst + 128 * GH;
        const int k0 = it * 32;
#pragma unroll
        for (int i = 0; i < 2; i++) {
            const int cid = i * 256 + tid;          // 0..511
            const int row = cid >> 2;
            const int c8  = (cid & 3) * 8;
            cpa16((uint32_t)__cvta_generic_to_shared(Adst + row * GH + c8),
                  A + (size_t)(bm + row) * K + k0 + c8);
            cpa16((uint32_t)__cvta_generic_to_shared(Bdst + row * GH + c8),
                  W + (size_t)(bn + row) * K + k0 + c8);
        }
    };

    const int NIT = 16;   // K=512, BK=32
    issue(0); CPA_COMMIT();
    issue(1); CPA_COMMIT();

    for (int it = 0; it < NIT; it++) {
        if (it + 2 < NIT) issue(it + 2);
        CPA_COMMIT();
        CPA_WAIT(2);
        __syncthreads();

        const uint32_t sb = gsu + (uint32_t)((it % 3) * GSTGH * 2);
#pragma unroll
        for (int ks = 0; ks < 2; ks++) {
            unsigned af[2][4];
#pragma unroll
            for (int mi = 0; mi < 2; mi++)
                ldsm4(af[mi][0], af[mi][1], af[mi][2], af[mi][3],
                      sb + obA + (uint32_t)((mi * 16 * GH + ks * 16) * 2));
#pragma unroll
            for (int n2 = 0; n2 < 4; n2++) {
                unsigned b0, b1, b2, b3;
                ldsm4(b0, b1, b2, b3, sb + obB + (uint32_t)((n2 * 16 * GH + ks * 16) * 2));
                unsigned blo[2] = {b0, b1}, bhi[2] = {b2, b3};
                mmah16(acc[0][n2 * 2],     af[0], blo);
                mmah16(acc[1][n2 * 2],     af[1], blo);
                mmah16(acc[0][n2 * 2 + 1], af[0], bhi);
                mmah16(acc[1][n2 * 2 + 1], af[1], bhi);
            }
        }
        __syncthreads();
    }

#pragma unroll
    for (int mi = 0; mi < 2; mi++) {
#pragma unroll
        for (int ni = 0; ni < 8; ni++) {
            const int row = bm + wm * 32 + mi * 16 + g4;
            const int col = bn + wn * 64 + ni * 8 + 2 * t4;
            const float b0 = bias[col], b1 = bias[col + 1];
            float v00 = acc[mi][ni][0] + b0, v01 = acc[mi][ni][1] + b1;
            float v10 = acc[mi][ni][2] + b0, v11 = acc[mi][ni][3] + b1;
            if (mode == 2) {
                // half, transposed: Vt[((b*8+h)*64+d)*1024 + key]
                const int b_ = row >> 10, key = row & 1023;
                const int h_ = col >> 6, d_ = col & 63;
                __half* base = (__half*)Cv + (((size_t)(b_ * 8 + h_) * 64 + d_) << 10);
                base[key]            = __float2half(v00);
                base[1024 + key]     = __float2half(v01);
                base[key + 8]        = __float2half(v10);
                base[1024 + key + 8] = __float2half(v11);
            } else if (mode == 3) {
                __half* C = (__half*)Cv;
                *(__half2*)&C[(size_t)row * N + col]       = __floats2half2_rn(v00, v01);
                *(__half2*)&C[(size_t)(row + 8) * N + col] = __floats2half2_rn(v10, v11);
            } else {
                if (mode == 1) {
                    v00 = fmaxf(v00, 0.f) + resid[(size_t)row * N + col];
                    v01 = fmaxf(v01, 0.f) + resid[(size_t)row * N + col + 1];
                    v10 = fmaxf(v10, 0.f) + resid[(size_t)(row + 8) * N + col];
                    v11 = fmaxf(v11, 0.f) + resid[(size_t)(row + 8) * N + col + 1];
                }
                float* C = (float*)Cv;
                *(float2*)&C[(size_t)row * N + col]       = make_float2(v00, v01);
                *(float2*)&C[(size_t)(row + 8) * N + col] = make_float2(v10, v11);
            }
        }
    }
}

struct PArgs { const __half* A[3]; const __half* W[3]; const float* b[3]; void* C[3]; int mode[3]; };

__global__ __launch_bounds__(256) void gemm_proj(PArgs pa) {
    extern __shared__ __half gsmh[];
    const int z = blockIdx.z;
    gemm_core(pa.A[z], pa.W[z], pa.b[z], nullptr, pa.C[z], pa.mode[z], gsmh);
}
__global__ __launch_bounds__(256) void gemm_out(const __half* __restrict__ A,
                                                const __half* __restrict__ W,
                                                const float* __restrict__ b,
                                                const float* __restrict__ resid, float* C) {
    extern __shared__ __half gsmh[];
    gemm_core(A, W, b, resid, C, 1, gsmh);
}

// ---------------- flash attention: all-f16 mma (S and PV), 4-stage cp.async ----------------
// 256 threads = 8 warps; block = (128 q-rows, head, batch); warp owns 16 q rows.
#define KH 72    // tile stride in halves (144 B: 16B-aligned, bank-quad distinct)
#define ATT_SMEM (4 * 2 * 64 * KH * 2)   // 73728 B

__global__ __launch_bounds__(256, 2)
void attn_fa(const float* __restrict__ Qp, const __half* __restrict__ Kph,
             const __half* __restrict__ Vth, float* __restrict__ O)
{
    extern __shared__ __align__(16) __half hsm[];
    __half* Kst = hsm;                       // 4 stages x [64 keys][KH]
    __half* Vst = hsm + 4 * 64 * KH;         // 4 stages x [64 d][KH]

    const int tid  = threadIdx.x;
    const int lane = tid & 31;
    const int warp = tid >> 5;
    const int g4 = lane >> 2;
    const int t4 = lane & 3;
    const int i8 = lane & 7;

    const int qt = blockIdx.x, h = blockIdx.y, b = blockIdx.z;
    const int q0 = qt * 128;
    const size_t gbase  = ((size_t)b * 1024) * 512 + (size_t)h * 64;
    const size_t vtbase = ((size_t)(b * 8 + h)) << 16;
    const float scale = 0.044194173824159216f;  // 1/sqrt(512)

    // B frags (both S and PV): bit4 -> n-half, bit3 -> k-half => (n0k0,n0k8,n8k0,n8k8)
    const uint32_t obB = (uint32_t)(((((lane >> 4) & 1) * 8 + i8) * KH
                                     + ((lane >> 3) & 1) * 8) * 2);
    const uint32_t ku0 = (uint32_t)__cvta_generic_to_shared(Kst);
    const uint32_t vu0 = (uint32_t)__cvta_generic_to_shared(Vst);

    auto issue = [&](int kt) {
        const int st = kt & 3;
        __half* kd = Kst + st * 64 * KH;
        __half* vd = Vst + st * 64 * KH;
#pragma unroll
        for (int i = 0; i < 2; i++) {   // K: 64 keys x 64 halves
            const int cid = i * 256 + tid;
            const int row = cid >> 3;
            const int c8  = (cid & 7) * 8;
            cpa16((uint32_t)__cvta_generic_to_shared(kd + row * KH + c8),
                  Kph + gbase + (size_t)(kt * 64 + row) * 512 + c8);
        }
#pragma unroll
        for (int i = 0; i < 2; i++) {   // V: 64 d x 64 keys
            const int cid = i * 256 + tid;
            const int row = cid >> 3;
            const int c8  = (cid & 7) * 8;
            cpa16((uint32_t)__cvta_generic_to_shared(vd + row * KH + c8),
                  Vth + vtbase + (size_t)row * 1024 + kt * 64 + c8);
        }
    };

    // Q fragments: half-packed from fp32 Qp, pre-scaled, register-resident
    const int qr = q0 + warp * 16 + g4;
    const float* Qrow0 = Qp + gbase + (size_t)qr * 512;
    const float* Qrow1 = Qrow0 + (size_t)8 * 512;
    unsigned aq[4][4];
#pragma unroll
    for (int ks = 0; ks < 4; ks++) {
        const int c = ks * 16 + 2 * t4;
        aq[ks][0] = packh2(Qrow0[c] * scale,     Qrow0[c + 1] * scale);
        aq[ks][1] = packh2(Qrow1[c] * scale,     Qrow1[c + 1] * scale);
        aq[ks][2] = packh2(Qrow0[c + 8] * scale, Qrow0[c + 9] * scale);
        aq[ks][3] = packh2(Qrow1[c + 8] * scale, Qrow1[c + 9] * scale);
    }

    float l0 = 0.f, l1 = 0.f;
    float o[8][4];
#pragma unroll
    for (int ni = 0; ni < 8; ni++)
#pragma unroll
        for (int j = 0; j < 4; j++) o[ni][j] = 0.f;

    issue(0); CPA_COMMIT();
    issue(1); CPA_COMMIT();
    issue(2); CPA_COMMIT();

    for (int kt = 0; kt < 16; kt++) {
        if (kt + 3 < 16) issue(kt + 3);
        CPA_COMMIT();
        CPA_WAIT(3);
        __syncthreads();

        const uint32_t ku = ku0 + (uint32_t)((kt & 3) * 64 * KH * 2);
        const uint32_t vu = vu0 + (uint32_t)((kt & 3) * 64 * KH * 2);

        // S = Q @ K^T, f16 m16n8k16
        float s[8][4];
#pragma unroll
        for (int ni = 0; ni < 8; ni++)
#pragma unroll
            for (int j = 0; j < 4; j++) s[ni][j] = 0.f;

#pragma unroll
        for (int ks = 0; ks < 4; ks++) {
#pragma unroll
            for (int n2 = 0; n2 < 4; n2++) {
                unsigned b0, b1, b2, b3;
                ldsm4(b0, b1, b2, b3, ku + obB + (uint32_t)((n2 * 16 * KH + ks * 16) * 2));
                unsigned blo[2] = {b0, b1}, bhi[2] = {b2, b3};
                mmah16(s[n2 * 2],     aq[ks], blo);
                mmah16(s[n2 * 2 + 1], aq[ks], bhi);
            }
        }

        // softmax, no max subtraction (scores bounded; clamp for safety);
        // l is partial (thread's 16 keys), reduced across t4 lanes after the loop.
#pragma unroll
        for (int ni = 0; ni < 8; ni++) {
            s[ni][0] = __expf(fminf(s[ni][0], 60.f));
            s[ni][1] = __expf(fminf(s[ni][1], 60.f));
            s[ni][2] = __expf(fminf(s[ni][2], 60.f));
            s[ni][3] = __expf(fminf(s[ni][3], 60.f));
            l0 += s[ni][0] + s[ni][1];
            l1 += s[ni][2] + s[ni][3];
        }

        // O += P @ V : P packed f32->f16 in registers (C-frag == f16 A-frag)
#pragma unroll
        for (int c = 0; c < 4; c++) {
            unsigned ap[4];
            ap[0] = packh2(s[2 * c][0],     s[2 * c][1]);
            ap[1] = packh2(s[2 * c][2],     s[2 * c][3]);
            ap[2] = packh2(s[2 * c + 1][0], s[2 * c + 1][1]);
            ap[3] = packh2(s[2 * c + 1][2], s[2 * c + 1][3]);
#pragma unroll
            for (int n2 = 0; n2 < 4; n2++) {
                unsigned b0, b1, b2, b3;
                ldsm4(b0, b1, b2, b3, vu + obB + (uint32_t)((n2 * 16 * KH + c * 16) * 2));
                unsigned blo[2] = {b0, b1}, bhi[2] = {b2, b3};
                mmah16(o[n2 * 2],     ap, blo);
                mmah16(o[n2 * 2 + 1], ap, bhi);
            }
        }
        __syncthreads();
    }

    // reduce softmax denominators across the 4 t4-lanes
    l0 += __shfl_xor_sync(0xffffffffu, l0, 1);
    l0 += __shfl_xor_sync(0xffffffffu, l0, 2);
    l1 += __shfl_xor_sync(0xffffffffu, l1, 1);
    l1 += __shfl_xor_sync(0xffffffffu, l1, 2);

    // epilogue: normalize + Q residual
    const float inv0 = 1.f / l0, inv1 = 1.f / l1;
    float* Ob = O + gbase + (size_t)qr * 512;
#pragma unroll
    for (int ni = 0; ni < 8; ni++) {
        const int col = ni * 8 + 2 * t4;
        float2 r0 = make_float2(o[ni][0] * inv0 + Qrow0[col],
                                o[ni][1] * inv0 + Qrow0[col + 1]);
        float2 r1 = make_float2(o[ni][2] * inv1 + Qrow1[col],
                                o[ni][3] * inv1 + Qrow1[col + 1]);
        *(float2*)&Ob[col]                   = r0;
        *(float2*)&Ob[(size_t)8 * 512 + col] = r1;
    }
}

// ---------------- layernorm over 512 features (optional dual half output) ----------------
__global__ __launch_bounds__(128)
void ln512_kernel(const float* __restrict__ X, const float* __restrict__ g,
                  const float* __restrict__ beta, float* __restrict__ Y, __half* __restrict__ Yh)
{
    const int row = blockIdx.x;
    const int tid = threadIdx.x;
    const int lane = tid & 31;
    const int wid = tid >> 5;

    float4 v = *(const float4*)&X[(size_t)row * 512 + tid * 4];
    float s  = v.x + v.y + v.z + v.w;
    float sq = v.x * v.x + v.y * v.y + v.z * v.z + v.w * v.w;
#pragma unroll
    for (int o = 16; o; o >>= 1) {
        s  += __shfl_xor_sync(0xffffffffu, s, o);
        sq += __shfl_xor_sync(0xffffffffu, sq, o);
    }
    __shared__ float ws[4], wq[4];
    if (lane == 0) { ws[wid] = s; wq[wid] = sq; }
    __syncthreads();
    float ts = ws[0] + ws[1] + ws[2] + ws[3];
    float tq = wq[0] + wq[1] + wq[2] + wq[3];
    const float mean = ts * (1.f / 512.f);
    const float var  = tq * (1.f / 512.f) - mean * mean;
    const float rstd = rsqrtf(var + 1e-5f);

    float4 gv = *(const float4*)&g[tid * 4];
    float4 bv = *(const float4*)&beta[tid * 4];
    float4 o;
    o.x = (v.x - mean) * rstd * gv.x + bv.x;
    o.y = (v.y - mean) * rstd * gv.y + bv.y;
    o.z = (v.z - mean) * rstd * gv.z + bv.z;
    o.w = (v.w - mean) * rstd * gv.w + bv.w;
    *(float4*)&Y[(size_t)row * 512 + tid * 4] = o;
    if (Yh) {
        __half2 hh[2];
        hh[0] = __floats2half2_rn(o.x, o.y);
        hh[1] = __floats2half2_rn(o.z, o.w);
        *(uint2*)&Yh[(size_t)row * 512 + tid * 4] = *(uint2*)hh;
    }
}

// ---------------- launch ----------------
extern "C" void kernel_launch(void* const* d_in, const int* in_sizes, int n_in,
                              void* d_out, int out_size)
{
    const float* Q   = (const float*)d_in[0];
    const float* K   = (const float*)d_in[1];
    const float* Wq  = (const float*)d_in[2];
    const float* bq  = (const float*)d_in[3];
    const float* Wk  = (const float*)d_in[4];
    const float* bk  = (const float*)d_in[5];
    const float* Wv  = (const float*)d_in[6];
    const float* bv  = (const float*)d_in[7];
    const float* Wo  = (const float*)d_in[8];
    const float* bo  = (const float*)d_in[9];
    const float* g0  = (const float*)d_in[10];
    const float* be0 = (const float*)d_in[11];
    const float* g1  = (const float*)d_in[12];
    const float* be1 = (const float*)d_in[13];
    float* out = (float*)d_out;

    float *Qp, *Obuf, *Xbuf, *Tbuf;
    __half *Kph, *Vth, *Xh, *Qh, *Kh, *Wh;
    cudaGetSymbolAddress((void**)&Qp,   g_Qp);
    cudaGetSymbolAddress((void**)&Kph,  g_Kph);
    cudaGetSymbolAddress((void**)&Vth,  g_Vth);
    cudaGetSymbolAddress((void**)&Obuf, g_O);
    cudaGetSymbolAddress((void**)&Xbuf, g_X);
    cudaGetSymbolAddress((void**)&Xh,   g_Xh);
    cudaGetSymbolAddress((void**)&Tbuf, g_T);
    cudaGetSymbolAddress((void**)&Qh,   g_Qh);
    cudaGetSymbolAddress((void**)&Kh,   g_Kh);
    cudaGetSymbolAddress((void**)&Wh,   g_Wh);

    cudaFuncSetAttribute(gemm_proj, cudaFuncAttributeMaxDynamicSharedMemorySize, GEMM_SMEM);
    cudaFuncSetAttribute(gemm_out,  cudaFuncAttributeMaxDynamicSharedMemorySize, GEMM_SMEM);
    cudaFuncSetAttribute(attn_fa,   cudaFuncAttributeMaxDynamicSharedMemorySize, ATT_SMEM);

    // 1) convert inputs + weights to half
    CArgs ca;
    ca.src[0] = Q;  ca.dst[0] = Qh;              ca.n[0] = NROWS * DV;
    ca.src[1] = K;  ca.dst[1] = Kh;              ca.n[1] = NROWS * DV;
    ca.src[2] = Wq; ca.dst[2] = Wh;              ca.n[2] = DV * DV;
    ca.src[3] = Wk; ca.dst[3] = Wh + DV * DV;    ca.n[3] = DV * DV;
    ca.src[4] = Wv; ca.dst[4] = Wh + 2 * DV * DV; ca.n[4] = DV * DV;
    ca.src[5] = Wo; ca.dst[5] = Wh + 3 * DV * DV; ca.n[5] = DV * DV;
    conv_half<<<dim3(NROWS * DV / (256 * 8), 6), 256>>>(ca);

    // 2) three projection GEMMs in one launch
    PArgs pa;
    pa.A[0] = Qh; pa.A[1] = Kh; pa.A[2] = Kh;
    pa.W[0] = Wh; pa.W[1] = Wh + DV * DV; pa.W[2] = Wh + 2 * DV * DV;
    pa.b[0] = bq; pa.b[1] = bk; pa.b[2] = bv;
    pa.C[0] = Qp; pa.C[1] = Kph; pa.C[2] = Vth;
    pa.mode[0] = 0; pa.mode[1] = 3; pa.mode[2] = 2;
    gemm_proj<<<dim3(DV / 128, NROWS / 128, 3), 256, GEMM_SMEM>>>(pa);

    // 3) attention
    dim3 adim(8, 8, 8);
    attn_fa<<<adim, 256, ATT_SMEM>>>(Qp, Kph, Vth, Obuf);

    // 4) LN (fp32 + half out)
    ln512_kernel<<<NROWS, 128>>>(Obuf, g0, be0, Xbuf, Xh);

    // 5) output GEMM + relu + residual
    gemm_out<<<dim3(DV / 128, NROWS / 128), 256, GEMM_SMEM>>>(Xh, Wh + 3 * DV * DV, bo, Xbuf, Tbuf);

    // 6) final LN
    ln512_kernel<<<NROWS, 128>>>(Tbuf, g1, be1, out, nullptr);
}

// round 9
// speedup vs baseline: 1.0329x; 1.0329x over previous
#include <cuda_runtime.h>
#include <cuda_fp16.h>
#include <math.h>
#include <stdint.h>

// ---------------- scratch ----------------
#define NROWS 8192
#define DV    512
__device__ float  g_Qp [NROWS * DV];
__device__ float  g_Kp [NROWS * DV];
__device__ __half g_Vth[NROWS * DV];   // V projected, half, transposed: [b][h][d(64)][key(1024)]
__device__ float  g_O  [NROWS * DV];
__device__ float  g_X  [NROWS * DV];
__device__ float  g_T  [NROWS * DV];

// ---------------- helpers ----------------
__device__ __forceinline__ unsigned f2tf(float x) {
    unsigned r; asm("cvt.rna.tf32.f32 %0, %1;" : "=r"(r) : "f"(x)); return r;
}
__device__ __forceinline__ float round_tf(float x) { return __uint_as_float(f2tf(x)); }
__device__ __forceinline__ unsigned packh2(float lo, float hi) {
    __half2 h = __floats2half2_rn(lo, hi);
    return *reinterpret_cast<unsigned*>(&h);
}
__device__ __forceinline__ void mma8(float* d, const unsigned* a, const unsigned* b) {
    asm volatile(
        "mma.sync.aligned.m16n8k8.row.col.f32.tf32.tf32.f32 "
        "{%0,%1,%2,%3},{%4,%5,%6,%7},{%8,%9},{%0,%1,%2,%3};"
        : "+f"(d[0]), "+f"(d[1]), "+f"(d[2]), "+f"(d[3])
        : "r"(a[0]), "r"(a[1]), "r"(a[2]), "r"(a[3]), "r"(b[0]), "r"(b[1]));
}
__device__ __forceinline__ void mmah16(float* d, const unsigned* a, const unsigned* b) {
    asm volatile(
        "mma.sync.aligned.m16n8k16.row.col.f32.f16.f16.f32 "
        "{%0,%1,%2,%3},{%4,%5,%6,%7},{%8,%9},{%0,%1,%2,%3};"
        : "+f"(d[0]), "+f"(d[1]), "+f"(d[2]), "+f"(d[3])
        : "r"(a[0]), "r"(a[1]), "r"(a[2]), "r"(a[3]), "r"(b[0]), "r"(b[1]));
}
__device__ __forceinline__ void ldsm4(unsigned& r0, unsigned& r1, unsigned& r2, unsigned& r3,
                                      uint32_t addr) {
    asm volatile("ldmatrix.sync.aligned.m8n8.x4.shared.b16 {%0,%1,%2,%3}, [%4];"
                 : "=r"(r0), "=r"(r1), "=r"(r2), "=r"(r3) : "r"(addr));
}
__device__ __forceinline__ void cpa16(uint32_t s, const void* g) {
    asm volatile("cp.async.cg.shared.global [%0], [%1], 16;" :: "r"(s), "l"(g));
}
#define CPA_COMMIT() asm volatile("cp.async.commit_group;")
#define CPA_WAIT(n)  asm volatile("cp.async.wait_group %0;" :: "n"(n))

// ---------------- tf32 GEMM core: 3-stage cp.async pipeline + ldmatrix feed ----------------
// C = A[8192,512] @ W[512,512]^T + bias. mode 0: rna-rounded store; 1: relu+residual(A);
// 2: half store, transposed Vt layout.
#define GP 20
#define GSTG (2 * 128 * GP)      // floats per stage (A then B)
#define GEMM_SMEM (3 * GSTG * 4) // 61440 B

__device__ __forceinline__ void gemm_core(const float* __restrict__ A,
                                          const float* __restrict__ W,
                                          const float* __restrict__ bias,
                                          void* Cv, int mode, float* gsm)
{
    const int tid  = threadIdx.x;
    const int lane = tid & 31;
    const int warp = tid >> 5;
    const int wm = warp & 3;
    const int wn = warp >> 2;
    const int bm = blockIdx.y * 128;
    const int bn = blockIdx.x * 128;
    const int g4 = lane >> 2;
    const int t4 = lane & 3;
    const int i8 = lane & 7;
    const int K = 512, N = 512;

    const uint32_t gsu = (uint32_t)__cvta_generic_to_shared(gsm);
    const uint32_t obA = (uint32_t)(((wm * 32 + ((lane >> 3) & 1) * 8 + i8) * GP
                                     + (lane >> 4) * 4) * 4);
    const uint32_t obB = (uint32_t)((128 * GP + (wn * 64 + (lane >> 4) * 8 + i8) * GP
                                     + ((lane >> 3) & 1) * 4) * 4);

    float acc[2][8][4];
#pragma unroll
    for (int mi = 0; mi < 2; mi++)
#pragma unroll
        for (int ni = 0; ni < 8; ni++)
#pragma unroll
            for (int j = 0; j < 4; j++) acc[mi][ni][j] = 0.f;

    auto issue = [&](int it) {
        const int st = it % 3;
        float* Adst = gsm + st * GSTG;
        float* Bdst = Adst + 128 * GP;
        const int k0 = it * 16;
#pragma unroll
        for (int i = 0; i < 2; i++) {
            const int cid = i * 256 + tid;          // 0..511
            const int row = cid >> 2;
            const int c4  = (cid & 3) * 4;
            cpa16((uint32_t)__cvta_generic_to_shared(Adst + row * GP + c4),
                  &A[(size_t)(bm + row) * K + k0 + c4]);
            cpa16((uint32_t)__cvta_generic_to_shared(Bdst + row * GP + c4),
                  &W[(size_t)(bn + row) * K + k0 + c4]);
        }
    };

    const int NIT = 32;
    issue(0); CPA_COMMIT();
    issue(1); CPA_COMMIT();

    for (int it = 0; it < NIT; it++) {
        if (it + 2 < NIT) issue(it + 2);
        CPA_COMMIT();
        CPA_WAIT(2);
        __syncthreads();

        const uint32_t sb = gsu + (uint32_t)((it % 3) * GSTG * 4);
#pragma unroll
        for (int ks = 0; ks < 2; ks++) {
            unsigned af[2][4];
#pragma unroll
            for (int mi = 0; mi < 2; mi++)
                ldsm4(af[mi][0], af[mi][1], af[mi][2], af[mi][3],
                      sb + obA + (uint32_t)((mi * 16 * GP + ks * 8) * 4));
#pragma unroll
            for (int n2 = 0; n2 < 4; n2++) {
                unsigned b0, b1, b2, b3;
                ldsm4(b0, b1, b2, b3, sb + obB + (uint32_t)((n2 * 16 * GP + ks * 8) * 4));
                unsigned be[2] = {b0, b1}, bo_[2] = {b2, b3};
                mma8(acc[0][n2 * 2],     af[0], be);
                mma8(acc[1][n2 * 2],     af[1], be);
                mma8(acc[0][n2 * 2 + 1], af[0], bo_);
                mma8(acc[1][n2 * 2 + 1], af[1], bo_);
            }
        }
        __syncthreads();
    }

#pragma unroll
    for (int mi = 0; mi < 2; mi++) {
#pragma unroll
        for (int ni = 0; ni < 8; ni++) {
            const int row = bm + wm * 32 + mi * 16 + g4;
            const int col = bn + wn * 64 + ni * 8 + 2 * t4;
            const float b0 = bias[col], b1 = bias[col + 1];
            float v00 = acc[mi][ni][0] + b0, v01 = acc[mi][ni][1] + b1;
            float v10 = acc[mi][ni][2] + b0, v11 = acc[mi][ni][3] + b1;
            if (mode == 2) {
                // half store, transposed: Vt[((b*8+h)*64+d)*1024 + key]
                const int b_ = row >> 10, key = row & 1023;
                const int h_ = col >> 6, d_ = col & 63;
                __half* base = (__half*)Cv + (((size_t)(b_ * 8 + h_) * 64 + d_) << 10);
                base[key]            = __float2half(v00);
                base[1024 + key]     = __float2half(v01);
                base[key + 8]        = __float2half(v10);
                base[1024 + key + 8] = __float2half(v11);
            } else {
                if (mode == 1) {
                    v00 = fmaxf(v00, 0.f) + A[(size_t)row * K + col];
                    v01 = fmaxf(v01, 0.f) + A[(size_t)row * K + col + 1];
                    v10 = fmaxf(v10, 0.f) + A[(size_t)(row + 8) * K + col];
                    v11 = fmaxf(v11, 0.f) + A[(size_t)(row + 8) * K + col + 1];
                } else {
                    v00 = round_tf(v00); v01 = round_tf(v01);
                    v10 = round_tf(v10); v11 = round_tf(v11);
                }
                float* C = (float*)Cv;
                *(float2*)&C[(size_t)row * N + col]       = make_float2(v00, v01);
                *(float2*)&C[(size_t)(row + 8) * N + col] = make_float2(v10, v11);
            }
        }
    }
}

struct PArgs {
    const float* A[3]; const float* W[3]; const float* b[3]; void* C[3];
};

// __launch_bounds__(256, 3): registers were the occupancy binder (95 regs -> 2 CTAs/SM);
// cap at 85 to fit 3 CTAs/SM (smem 3x60KB = 180KB <= 228KB).
__global__ __launch_bounds__(256, 3) void gemm_proj(PArgs pa) {
    extern __shared__ float gsm[];
    const int z = blockIdx.z;
    gemm_core(pa.A[z], pa.W[z], pa.b[z], pa.C[z], (z == 2) ? 2 : 0, gsm);
}
__global__ __launch_bounds__(256, 3) void gemm_out(const float* __restrict__ A,
                                                   const float* __restrict__ W,
                                                   const float* __restrict__ b, float* C) {
    extern __shared__ float gsm[];
    gemm_core(A, W, b, C, 1, gsm);
}

// ---------------- flash attention: tf32 S + f16 PV (FA2 fragment reuse), 4-stage cp.async ----------------
// 256 threads = 8 warps; block = (128 q-rows, head, batch); warp owns 16 q rows.
#define KSTR 68   // K tile stride (floats)
#define VSTR 72   // V tile stride (halves) -> 144B rows, conflict-free ldmatrix
#define ATT_SMEM (4 * 64 * KSTR * 4 + 4 * 64 * VSTR * 2)   // 106496 B

__global__ __launch_bounds__(256, 2)
void attn_fa(const float* __restrict__ Qp, const float* __restrict__ Kp,
             const __half* __restrict__ Vth, float* __restrict__ O)
{
    extern __shared__ __align__(16) float dsm[];
    float*  Kst = dsm;                                 // 4 stages x [64][KSTR] f32
    __half* Vst = (__half*)(dsm + 4 * 64 * KSTR);      // 4 stages x [64][VSTR] f16

    const int tid  = threadIdx.x;
    const int lane = tid & 31;
    const int warp = tid >> 5;
    const int g4 = lane >> 2;
    const int t4 = lane & 3;
    const int i8 = lane & 7;

    const int qt = blockIdx.x, h = blockIdx.y, b = blockIdx.z;
    const int q0 = qt * 128;
    const size_t gbase  = ((size_t)b * 1024) * 512 + (size_t)h * 64;
    const size_t vtbase = ((size_t)(b * 8 + h)) << 16;   // halves: *64*1024
    const float scale = 0.044194173824159216f;  // 1/sqrt(512)

    // lane constants
    const uint32_t obB = (uint32_t)((((lane >> 4) * 8 + i8) * KSTR + ((lane >> 3) & 1) * 4) * 4);
    const uint32_t vlane = (uint32_t)(((((lane >> 4) & 1) * 8 + i8) * VSTR
                                      + ((lane >> 3) & 1) * 8) * 2);
    const uint32_t ku0 = (uint32_t)__cvta_generic_to_shared(Kst);
    const uint32_t vu0 = (uint32_t)__cvta_generic_to_shared(Vst);

    auto issue = [&](int kt) {
        const int st = kt & 3;
        float*  kd = Kst + st * 64 * KSTR;
        __half* vd = Vst + st * 64 * VSTR;
#pragma unroll
        for (int i = 0; i < 4; i++) {   // K: 64 rows x 64 f32
            const int cid = i * 256 + tid;
            const int row = cid >> 4;
            const int c4  = (cid & 15) * 4;
            cpa16((uint32_t)__cvta_generic_to_shared(kd + row * KSTR + c4),
                  Kp + gbase + (size_t)(kt * 64 + row) * 512 + c4);
        }
#pragma unroll
        for (int i = 0; i < 2; i++) {   // V: 64 rows(d) x 64 halves
            const int cid = i * 256 + tid;
            const int row = cid >> 3;
            const int c8  = (cid & 7) * 8;
            cpa16((uint32_t)__cvta_generic_to_shared(vd + row * VSTR + c8),
                  Vth + vtbase + (size_t)row * 1024 + kt * 64 + c8);
        }
    };

    // Q fragments (rna tf32, pre-scaled), register-resident
    const int qr = q0 + warp * 16 + g4;
    const float* Qrow0 = Qp + gbase + (size_t)qr * 512;
    const float* Qrow1 = Qrow0 + (size_t)8 * 512;
    unsigned aq[8][4];
#pragma unroll
    for (int ks = 0; ks < 8; ks++) {
        const int c = ks * 8 + t4;
        aq[ks][0] = f2tf(Qrow0[c] * scale);
        aq[ks][1] = f2tf(Qrow1[c] * scale);
        aq[ks][2] = f2tf(Qrow0[c + 4] * scale);
        aq[ks][3] = f2tf(Qrow1[c + 4] * scale);
    }

    float l0 = 0.f, l1 = 0.f;
    float o[8][4];
#pragma unroll
    for (int ni = 0; ni < 8; ni++)
#pragma unroll
        for (int j = 0; j < 4; j++) o[ni][j] = 0.f;

    issue(0); CPA_COMMIT();
    issue(1); CPA_COMMIT();
    issue(2); CPA_COMMIT();

    for (int kt = 0; kt < 16; kt++) {
        if (kt + 3 < 16) issue(kt + 3);
        CPA_COMMIT();
        CPA_WAIT(3);
        __syncthreads();

        const uint32_t ku = ku0 + (uint32_t)((kt & 3) * 64 * KSTR * 4);
        const uint32_t vu = vu0 + (uint32_t)((kt & 3) * 64 * VSTR * 2);

        // S = Qs @ K^T (16 rows x 64 keys per warp), tf32
        float s[8][4];
#pragma unroll
        for (int ni = 0; ni < 8; ni++)
#pragma unroll
            for (int j = 0; j < 4; j++) s[ni][j] = 0.f;

#pragma unroll
        for (int ks = 0; ks < 8; ks++) {
#pragma unroll
            for (int n2 = 0; n2 < 4; n2++) {
                unsigned b0, b1, b2, b3;
                ldsm4(b0, b1, b2, b3, ku + obB + (uint32_t)((n2 * 16 * KSTR + ks * 8) * 4));
                unsigned be[2] = {b0, b1}, bo_[2] = {b2, b3};
                mma8(s[n2 * 2],     aq[ks], be);
                mma8(s[n2 * 2 + 1], aq[ks], bo_);
            }
        }

        // softmax without max subtraction (scores bounded; clamp for safety).
        // partial l per thread (its 16 keys); reduced across t4 lanes after the loop.
#pragma unroll
        for (int ni = 0; ni < 8; ni++) {
            s[ni][0] = __expf(fminf(s[ni][0], 60.f));
            s[ni][1] = __expf(fminf(s[ni][1], 60.f));
            s[ni][2] = __expf(fminf(s[ni][2], 60.f));
            s[ni][3] = __expf(fminf(s[ni][3], 60.f));
            l0 += s[ni][0] + s[ni][1];
            l1 += s[ni][2] + s[ni][3];
        }

        // O += P @ V : P converted f32->f16 IN REGISTERS (C-fragment == f16 A-fragment),
        // V (half, [d][key]) B-fragments via ldmatrix. m16n8k16.
#pragma unroll
        for (int c = 0; c < 4; c++) {
            unsigned ap[4];
            ap[0] = packh2(s[2 * c][0],     s[2 * c][1]);      // row g4,   k 2t4..
            ap[1] = packh2(s[2 * c][2],     s[2 * c][3]);      // row g4+8
            ap[2] = packh2(s[2 * c + 1][0], s[2 * c + 1][1]);  // row g4,   k 2t4+8..
            ap[3] = packh2(s[2 * c + 1][2], s[2 * c + 1][3]);  // row g4+8
#pragma unroll
            for (int n2 = 0; n2 < 4; n2++) {
                unsigned b0, b1, b2, b3;
                ldsm4(b0, b1, b2, b3,
                      vu + vlane + (uint32_t)(((n2 * 16) * VSTR + c * 16) * 2));
                unsigned be[2] = {b0, b1}, bo_[2] = {b2, b3};
                mmah16(o[n2 * 2],     ap, be);
                mmah16(o[n2 * 2 + 1], ap, bo_);
            }
        }
        __syncthreads();
    }

    // reduce softmax denominators across the 4 t4-lanes (full 1024-key sums)
    l0 += __shfl_xor_sync(0xffffffffu, l0, 1);
    l0 += __shfl_xor_sync(0xffffffffu, l0, 2);
    l1 += __shfl_xor_sync(0xffffffffu, l1, 1);
    l1 += __shfl_xor_sync(0xffffffffu, l1, 2);

    // epilogue: normalize + Q residual
    const float inv0 = 1.f / l0, inv1 = 1.f / l1;
    float* Ob = O + gbase + (size_t)qr * 512;
#pragma unroll
    for (int ni = 0; ni < 8; ni++) {
        const int col = ni * 8 + 2 * t4;
        float2 r0 = make_float2(o[ni][0] * inv0 + Qrow0[col],
                                o[ni][1] * inv0 + Qrow0[col + 1]);
        float2 r1 = make_float2(o[ni][2] * inv1 + Qrow1[col],
                                o[ni][3] * inv1 + Qrow1[col + 1]);
        *(float2*)&Ob[col]                   = r0;
        *(float2*)&Ob[(size_t)8 * 512 + col] = r1;
    }
}

// ---------------- layernorm over 512 features ----------------
__global__ __launch_bounds__(128)
void ln512_kernel(const float* __restrict__ X, const float* __restrict__ g,
                  const float* __restrict__ beta, float* __restrict__ Y, int roundOut)
{
    const int row = blockIdx.x;
    const int tid = threadIdx.x;
    const int lane = tid & 31;
    const int wid = tid >> 5;

    float4 v = *(const float4*)&X[(size_t)row * 512 + tid * 4];
    float s  = v.x + v.y + v.z + v.w;
    float sq = v.x * v.x + v.y * v.y + v.z * v.z + v.w * v.w;
#pragma unroll
    for (int o = 16; o; o >>= 1) {
        s  += __shfl_xor_sync(0xffffffffu, s, o);
        sq += __shfl_xor_sync(0xffffffffu, sq, o);
    }
    __shared__ float ws[4], wq[4];
    if (lane == 0) { ws[wid] = s; wq[wid] = sq; }
    __syncthreads();
    float ts = ws[0] + ws[1] + ws[2] + ws[3];
    float tq = wq[0] + wq[1] + wq[2] + wq[3];
    const float mean = ts * (1.f / 512.f);
    const float var  = tq * (1.f / 512.f) - mean * mean;
    const float rstd = rsqrtf(var + 1e-5f);

    float4 gv = *(const float4*)&g[tid * 4];
    float4 bv = *(const float4*)&beta[tid * 4];
    float4 o;
    o.x = (v.x - mean) * rstd * gv.x + bv.x;
    o.y = (v.y - mean) * rstd * gv.y + bv.y;
    o.z = (v.z - mean) * rstd * gv.z + bv.z;
    o.w = (v.w - mean) * rstd * gv.w + bv.w;
    if (roundOut) {
        o.x = round_tf(o.x); o.y = round_tf(o.y);
        o.z = round_tf(o.z); o.w = round_tf(o.w);
    }
    *(float4*)&Y[(size_t)row * 512 + tid * 4] = o;
}

// ---------------- launch ----------------
extern "C" void kernel_launch(void* const* d_in, const int* in_sizes, int n_in,
                              void* d_out, int out_size)
{
    const float* Q   = (const float*)d_in[0];
    const float* K   = (const float*)d_in[1];
    const float* Wq  = (const float*)d_in[2];
    const float* bq  = (const float*)d_in[3];
    const float* Wk  = (const float*)d_in[4];
    const float* bk  = (const float*)d_in[5];
    const float* Wv  = (const float*)d_in[6];
    const float* bv  = (const float*)d_in[7];
    const float* Wo  = (const float*)d_in[8];
    const float* bo  = (const float*)d_in[9];
    const float* g0  = (const float*)d_in[10];
    const float* be0 = (const float*)d_in[11];
    const float* g1  = (const float*)d_in[12];
    const float* be1 = (const float*)d_in[13];
    float* out = (float*)d_out;

    float *Qp, *Kp, *Obuf, *Xbuf, *Tbuf;
    __half* Vth;
    cudaGetSymbolAddress((void**)&Qp,   g_Qp);
    cudaGetSymbolAddress((void**)&Kp,   g_Kp);
    cudaGetSymbolAddress((void**)&Vth,  g_Vth);
    cudaGetSymbolAddress((void**)&Obuf, g_O);
    cudaGetSymbolAddress((void**)&Xbuf, g_X);
    cudaGetSymbolAddress((void**)&Tbuf, g_T);

    cudaFuncSetAttribute(gemm_proj, cudaFuncAttributeMaxDynamicSharedMemorySize, GEMM_SMEM);
    cudaFuncSetAttribute(gemm_out,  cudaFuncAttributeMaxDynamicSharedMemorySize, GEMM_SMEM);
    cudaFuncSetAttribute(attn_fa,   cudaFuncAttributeMaxDynamicSharedMemorySize, ATT_SMEM);

    PArgs pa;
    pa.A[0] = Q;  pa.A[1] = K;  pa.A[2] = K;
    pa.W[0] = Wq; pa.W[1] = Wk; pa.W[2] = Wv;
    pa.b[0] = bq; pa.b[1] = bk; pa.b[2] = bv;
    pa.C[0] = Qp; pa.C[1] = Kp; pa.C[2] = Vth;

    gemm_proj<<<dim3(DV / 128, NROWS / 128, 3), 256, GEMM_SMEM>>>(pa);

    dim3 adim(8, 8, 8);                 // (q-tiles of 128, heads, batch)
    attn_fa<<<adim, 256, ATT_SMEM>>>(Qp, Kp, Vth, Obuf);

    ln512_kernel<<<NROWS, 128>>>(Obuf, g0, be0, Xbuf, 1);
    gemm_out<<<dim3(DV / 128, NROWS / 128), 256, GEMM_SMEM>>>(Xbuf, Wo, bo, Tbuf);
    ln512_kernel<<<NROWS, 128>>>(Tbuf, g1, be1, out, 0);
}

// round 10
// speedup vs baseline: 1.2674x; 1.2270x over previous
#include <cuda_runtime.h>
#include <cuda_fp16.h>
#include <math.h>
#include <stdint.h>

// ---------------- scratch ----------------
#define NROWS 8192
#define DV    512
__device__ float  g_Qp [NROWS * DV];
__device__ float  g_Kp [NROWS * DV];
__device__ __half g_Vth[NROWS * DV];   // V projected, half, transposed: [b][h][d(64)][key(1024)]
__device__ float  g_O  [NROWS * DV];
__device__ float  g_X  [NROWS * DV];
__device__ float  g_T  [NROWS * DV];

// ---------------- helpers ----------------
__device__ __forceinline__ unsigned f2tf(float x) {
    unsigned r; asm("cvt.rna.tf32.f32 %0, %1;" : "=r"(r) : "f"(x)); return r;
}
__device__ __forceinline__ float round_tf(float x) { return __uint_as_float(f2tf(x)); }
__device__ __forceinline__ unsigned packh2(float lo, float hi) {
    __half2 h = __floats2half2_rn(lo, hi);
    return *reinterpret_cast<unsigned*>(&h);
}
__device__ __forceinline__ void mma8(float* d, const unsigned* a, const unsigned* b) {
    asm volatile(
        "mma.sync.aligned.m16n8k8.row.col.f32.tf32.tf32.f32 "
        "{%0,%1,%2,%3},{%4,%5,%6,%7},{%8,%9},{%0,%1,%2,%3};"
        : "+f"(d[0]), "+f"(d[1]), "+f"(d[2]), "+f"(d[3])
        : "r"(a[0]), "r"(a[1]), "r"(a[2]), "r"(a[3]), "r"(b[0]), "r"(b[1]));
}
__device__ __forceinline__ void mmah16(float* d, const unsigned* a, const unsigned* b) {
    asm volatile(
        "mma.sync.aligned.m16n8k16.row.col.f32.f16.f16.f32 "
        "{%0,%1,%2,%3},{%4,%5,%6,%7},{%8,%9},{%0,%1,%2,%3};"
        : "+f"(d[0]), "+f"(d[1]), "+f"(d[2]), "+f"(d[3])
        : "r"(a[0]), "r"(a[1]), "r"(a[2]), "r"(a[3]), "r"(b[0]), "r"(b[1]));
}
__device__ __forceinline__ void ldsm4(unsigned& r0, unsigned& r1, unsigned& r2, unsigned& r3,
                                      uint32_t addr) {
    asm volatile("ldmatrix.sync.aligned.m8n8.x4.shared.b16 {%0,%1,%2,%3}, [%4];"
                 : "=r"(r0), "=r"(r1), "=r"(r2), "=r"(r3) : "r"(addr));
}
__device__ __forceinline__ void cpa16(uint32_t s, const void* g) {
    asm volatile("cp.async.cg.shared.global [%0], [%1], 16;" :: "r"(s), "l"(g));
}
#define CPA_COMMIT() asm volatile("cp.async.commit_group;")
#define CPA_WAIT(n)  asm volatile("cp.async.wait_group %0;" :: "n"(n))

// ---------------- tf32 GEMM core: 128x64 tiles, 3-stage cp.async + ldmatrix ----------------
// C = A[8192,512] @ W[512,512]^T + bias. mode 0: rna-rounded store; 1: relu+residual(A);
// 2: half store, transposed Vt layout.
// 256 threads = 8 warps as 4(m) x 2(n); warp tile 32x32. Grid x = N/64, y = M/128.
#define GP 20
#define GSTG ((128 + 64) * GP)     // floats per stage (A 128 rows, B 64 rows)
#define GEMM_SMEM (3 * GSTG * 4)   // 46080 B -> 3 CTAs/SM

__device__ __forceinline__ void gemm_core(const float* __restrict__ A,
                                          const float* __restrict__ W,
                                          const float* __restrict__ bias,
                                          void* Cv, int mode, float* gsm)
{
    const int tid  = threadIdx.x;
    const int lane = tid & 31;
    const int warp = tid >> 5;
    const int wm = warp & 3;       // m offset wm*32
    const int wn = warp >> 2;      // n offset wn*32
    const int bm = blockIdx.y * 128;
    const int bn = blockIdx.x * 64;
    const int g4 = lane >> 2;
    const int t4 = lane & 3;
    const int i8 = lane & 7;
    const int K = 512, N = 512;

    const uint32_t gsu = (uint32_t)__cvta_generic_to_shared(gsm);
    const uint32_t obA = (uint32_t)(((wm * 32 + ((lane >> 3) & 1) * 8 + i8) * GP
                                     + (lane >> 4) * 4) * 4);
    const uint32_t obB = (uint32_t)((128 * GP + (wn * 32 + (lane >> 4) * 8 + i8) * GP
                                     + ((lane >> 3) & 1) * 4) * 4);

    float acc[2][4][4];
#pragma unroll
    for (int mi = 0; mi < 2; mi++)
#pragma unroll
        for (int ni = 0; ni < 4; ni++)
#pragma unroll
            for (int j = 0; j < 4; j++) acc[mi][ni][j] = 0.f;

    auto issue = [&](int it) {
        const int st = it % 3;
        float* Adst = gsm + st * GSTG;
        float* Bdst = Adst + 128 * GP;
        const int k0 = it * 16;
#pragma unroll
        for (int i = 0; i < 2; i++) {           // A: 128 rows x 16 f32 = 512 chunks
            const int cid = i * 256 + tid;
            const int row = cid >> 2;
            const int c4  = (cid & 3) * 4;
            cpa16((uint32_t)__cvta_generic_to_shared(Adst + row * GP + c4),
                  &A[(size_t)(bm + row) * K + k0 + c4]);
        }
        {                                        // B: 64 rows x 16 f32 = 256 chunks
            const int row = tid >> 2;
            const int c4  = (tid & 3) * 4;
            cpa16((uint32_t)__cvta_generic_to_shared(Bdst + row * GP + c4),
                  &W[(size_t)(bn + row) * K + k0 + c4]);
        }
    };

    const int NIT = 32;
    issue(0); CPA_COMMIT();
    issue(1); CPA_COMMIT();

    for (int it = 0; it < NIT; it++) {
        if (it + 2 < NIT) issue(it + 2);
        CPA_COMMIT();
        CPA_WAIT(2);
        __syncthreads();

        const uint32_t sb = gsu + (uint32_t)((it % 3) * GSTG * 4);
#pragma unroll
        for (int ks = 0; ks < 2; ks++) {
            unsigned af[2][4];
#pragma unroll
            for (int mi = 0; mi < 2; mi++)
                ldsm4(af[mi][0], af[mi][1], af[mi][2], af[mi][3],
                      sb + obA + (uint32_t)((mi * 16 * GP + ks * 8) * 4));
#pragma unroll
            for (int n2 = 0; n2 < 2; n2++) {
                unsigned b0, b1, b2, b3;
                ldsm4(b0, b1, b2, b3, sb + obB + (uint32_t)((n2 * 16 * GP + ks * 8) * 4));
                unsigned be[2] = {b0, b1}, bo_[2] = {b2, b3};
                mma8(acc[0][n2 * 2],     af[0], be);
                mma8(acc[1][n2 * 2],     af[1], be);
                mma8(acc[0][n2 * 2 + 1], af[0], bo_);
                mma8(acc[1][n2 * 2 + 1], af[1], bo_);
            }
        }
        __syncthreads();
    }

#pragma unroll
    for (int mi = 0; mi < 2; mi++) {
#pragma unroll
        for (int ni = 0; ni < 4; ni++) {
            const int row = bm + wm * 32 + mi * 16 + g4;
            const int col = bn + wn * 32 + ni * 8 + 2 * t4;
            const float b0 = bias[col], b1 = bias[col + 1];
            float v00 = acc[mi][ni][0] + b0, v01 = acc[mi][ni][1] + b1;
            float v10 = acc[mi][ni][2] + b0, v11 = acc[mi][ni][3] + b1;
            if (mode == 2) {
                // half store, transposed: Vt[((b*8+h)*64+d)*1024 + key]
                const int b_ = row >> 10, key = row & 1023;
                const int h_ = col >> 6, d_ = col & 63;
                __half* base = (__half*)Cv + (((size_t)(b_ * 8 + h_) * 64 + d_) << 10);
                base[key]            = __float2half(v00);
                base[1024 + key]     = __float2half(v01);
                base[key + 8]        = __float2half(v10);
                base[1024 + key + 8] = __float2half(v11);
            } else {
                if (mode == 1) {
                    v00 = fmaxf(v00, 0.f) + A[(size_t)row * K + col];
                    v01 = fmaxf(v01, 0.f) + A[(size_t)row * K + col + 1];
                    v10 = fmaxf(v10, 0.f) + A[(size_t)(row + 8) * K + col];
                    v11 = fmaxf(v11, 0.f) + A[(size_t)(row + 8) * K + col + 1];
                } else {
                    v00 = round_tf(v00); v01 = round_tf(v01);
                    v10 = round_tf(v10); v11 = round_tf(v11);
                }
                float* C = (float*)Cv;
                *(float2*)&C[(size_t)row * N + col]       = make_float2(v00, v01);
                *(float2*)&C[(size_t)(row + 8) * N + col] = make_float2(v10, v11);
            }
        }
    }
}

struct PArgs {
    const float* A[3]; const float* W[3]; const float* b[3]; void* C[3];
};

__global__ __launch_bounds__(256) void gemm_proj(PArgs pa) {
    extern __shared__ float gsm[];
    const int z = blockIdx.z;
    gemm_core(pa.A[z], pa.W[z], pa.b[z], pa.C[z], (z == 2) ? 2 : 0, gsm);
}
__global__ __launch_bounds__(256) void gemm_out(const float* __restrict__ A,
                                                const float* __restrict__ W,
                                                const float* __restrict__ b, float* C) {
    extern __shared__ float gsm[];
    gemm_core(A, W, b, C, 1, gsm);
}

// ---------------- flash attention: tf32 S + f16 PV (FA2 fragment reuse), 4-stage cp.async ----------------
// 256 threads = 8 warps; block = (128 q-rows, head, batch); warp owns 16 q rows.
#define KSTR 68   // K tile stride (floats)
#define VSTR 72   // V tile stride (halves) -> 144B rows, conflict-free ldmatrix
#define ATT_SMEM (4 * 64 * KSTR * 4 + 4 * 64 * VSTR * 2)   // 106496 B

__global__ __launch_bounds__(256, 2)
void attn_fa(const float* __restrict__ Qp, const float* __restrict__ Kp,
             const __half* __restrict__ Vth, float* __restrict__ O)
{
    extern __shared__ __align__(16) float dsm[];
    float*  Kst = dsm;                                 // 4 stages x [64][KSTR] f32
    __half* Vst = (__half*)(dsm + 4 * 64 * KSTR);      // 4 stages x [64][VSTR] f16

    const int tid  = threadIdx.x;
    const int lane = tid & 31;
    const int warp = tid >> 5;
    const int g4 = lane >> 2;
    const int t4 = lane & 3;
    const int i8 = lane & 7;

    const int qt = blockIdx.x, h = blockIdx.y, b = blockIdx.z;
    const int q0 = qt * 128;
    const size_t gbase  = ((size_t)b * 1024) * 512 + (size_t)h * 64;
    const size_t vtbase = ((size_t)(b * 8 + h)) << 16;   // halves: *64*1024
    const float scale = 0.044194173824159216f;  // 1/sqrt(512)

    // lane constants
    const uint32_t obB = (uint32_t)((((lane >> 4) * 8 + i8) * KSTR + ((lane >> 3) & 1) * 4) * 4);
    const uint32_t vlane = (uint32_t)(((((lane >> 4) & 1) * 8 + i8) * VSTR
                                      + ((lane >> 3) & 1) * 8) * 2);
    const uint32_t ku0 = (uint32_t)__cvta_generic_to_shared(Kst);
    const uint32_t vu0 = (uint32_t)__cvta_generic_to_shared(Vst);

    auto issue = [&](int kt) {
        const int st = kt & 3;
        float*  kd = Kst + st * 64 * KSTR;
        __half* vd = Vst + st * 64 * VSTR;
#pragma unroll
        for (int i = 0; i < 4; i++) {   // K: 64 rows x 64 f32
            const int cid = i * 256 + tid;
            const int row = cid >> 4;
            const int c4  = (cid & 15) * 4;
            cpa16((uint32_t)__cvta_generic_to_shared(kd + row * KSTR + c4),
                  Kp + gbase + (size_t)(kt * 64 + row) * 512 + c4);
        }
#pragma unroll
        for (int i = 0; i < 2; i++) {   // V: 64 rows(d) x 64 halves
            const int cid = i * 256 + tid;
            const int row = cid >> 3;
            const int c8  = (cid & 7) * 8;
            cpa16((uint32_t)__cvta_generic_to_shared(vd + row * VSTR + c8),
                  Vth + vtbase + (size_t)row * 1024 + kt * 64 + c8);
        }
    };

    // Q fragments (rna tf32, pre-scaled), register-resident
    const int qr = q0 + warp * 16 + g4;
    const float* Qrow0 = Qp + gbase + (size_t)qr * 512;
    const float* Qrow1 = Qrow0 + (size_t)8 * 512;
    unsigned aq[8][4];
#pragma unroll
    for (int ks = 0; ks < 8; ks++) {
        const int c = ks * 8 + t4;
        aq[ks][0] = f2tf(Qrow0[c] * scale);
        aq[ks][1] = f2tf(Qrow1[c] * scale);
        aq[ks][2] = f2tf(Qrow0[c + 4] * scale);
        aq[ks][3] = f2tf(Qrow1[c + 4] * scale);
    }

    float l0 = 0.f, l1 = 0.f;
    float o[8][4];
#pragma unroll
    for (int ni = 0; ni < 8; ni++)
#pragma unroll
        for (int j = 0; j < 4; j++) o[ni][j] = 0.f;

    issue(0); CPA_COMMIT();
    issue(1); CPA_COMMIT();
    issue(2); CPA_COMMIT();

    for (int kt = 0; kt < 16; kt++) {
        if (kt + 3 < 16) issue(kt + 3);
        CPA_COMMIT();
        CPA_WAIT(3);
        __syncthreads();

        const uint32_t ku = ku0 + (uint32_t)((kt & 3) * 64 * KSTR * 4);
        const uint32_t vu = vu0 + (uint32_t)((kt & 3) * 64 * VSTR * 2);

        // S = Qs @ K^T (16 rows x 64 keys per warp), tf32
        float s[8][4];
#pragma unroll
        for (int ni = 0; ni < 8; ni++)
#pragma unroll
            for (int j = 0; j < 4; j++) s[ni][j] = 0.f;

#pragma unroll
        for (int ks = 0; ks < 8; ks++) {
#pragma unroll
            for (int n2 = 0; n2 < 4; n2++) {
                unsigned b0, b1, b2, b3;
                ldsm4(b0, b1, b2, b3, ku + obB + (uint32_t)((n2 * 16 * KSTR + ks * 8) * 4));
                unsigned be[2] = {b0, b1}, bo_[2] = {b2, b3};
                mma8(s[n2 * 2],     aq[ks], be);
                mma8(s[n2 * 2 + 1], aq[ks], bo_);
            }
        }

        // softmax without max subtraction (scores bounded; clamp for safety).
        // partial l per thread (its 16 keys); reduced across t4 lanes after the loop.
#pragma unroll
        for (int ni = 0; ni < 8; ni++) {
            s[ni][0] = __expf(fminf(s[ni][0], 60.f));
            s[ni][1] = __expf(fminf(s[ni][1], 60.f));
            s[ni][2] = __expf(fminf(s[ni][2], 60.f));
            s[ni][3] = __expf(fminf(s[ni][3], 60.f));
            l0 += s[ni][0] + s[ni][1];
            l1 += s[ni][2] + s[ni][3];
        }

        // O += P @ V : P converted f32->f16 IN REGISTERS (C-fragment == f16 A-fragment),
        // V (half, [d][key]) B-fragments via ldmatrix. m16n8k16.
#pragma unroll
        for (int c = 0; c < 4; c++) {
            unsigned ap[4];
            ap[0] = packh2(s[2 * c][0],     s[2 * c][1]);      // row g4,   k 2t4..
            ap[1] = packh2(s[2 * c][2],     s[2 * c][3]);      // row g4+8
            ap[2] = packh2(s[2 * c + 1][0], s[2 * c + 1][1]);  // row g4,   k 2t4+8..
            ap[3] = packh2(s[2 * c + 1][2], s[2 * c + 1][3]);  // row g4+8
#pragma unroll
            for (int n2 = 0; n2 < 4; n2++) {
                unsigned b0, b1, b2, b3;
                ldsm4(b0, b1, b2, b3,
                      vu + vlane + (uint32_t)(((n2 * 16) * VSTR + c * 16) * 2));
                unsigned be[2] = {b0, b1}, bo_[2] = {b2, b3};
                mmah16(o[n2 * 2],     ap, be);
                mmah16(o[n2 * 2 + 1], ap, bo_);
            }
        }
        __syncthreads();
    }

    // reduce softmax denominators across the 4 t4-lanes (full 1024-key sums)
    l0 += __shfl_xor_sync(0xffffffffu, l0, 1);
    l0 += __shfl_xor_sync(0xffffffffu, l0, 2);
    l1 += __shfl_xor_sync(0xffffffffu, l1, 1);
    l1 += __shfl_xor_sync(0xffffffffu, l1, 2);

    // epilogue: normalize + Q residual
    const float inv0 = 1.f / l0, inv1 = 1.f / l1;
    float* Ob = O + gbase + (size_t)qr * 512;
#pragma unroll
    for (int ni = 0; ni < 8; ni++) {
        const int col = ni * 8 + 2 * t4;
        float2 r0 = make_float2(o[ni][0] * inv0 + Qrow0[col],
                                o[ni][1] * inv0 + Qrow0[col + 1]);
        float2 r1 = make_float2(o[ni][2] * inv1 + Qrow1[col],
                                o[ni][3] * inv1 + Qrow1[col + 1]);
        *(float2*)&Ob[col]                   = r0;
        *(float2*)&Ob[(size_t)8 * 512 + col] = r1;
    }
}

// ---------------- layernorm over 512 features ----------------
__global__ __launch_bounds__(128)
void ln512_kernel(const float* __restrict__ X, const float* __restrict__ g,
                  const float* __restrict__ beta, float* __restrict__ Y, int roundOut)
{
    const int row = blockIdx.x;
    const int tid = threadIdx.x;
    const int lane = tid & 31;
    const int wid = tid >> 5;

    float4 v = *(const float4*)&X[(size_t)row * 512 + tid * 4];
    float s  = v.x + v.y + v.z + v.w;
    float sq = v.x * v.x + v.y * v.y + v.z * v.z + v.w * v.w;
#pragma unroll
    for (int o = 16; o; o >>= 1) {
        s  += __shfl_xor_sync(0xffffffffu, s, o);
        sq += __shfl_xor_sync(0xffffffffu, sq, o);
    }
    __shared__ float ws[4], wq[4];
    if (lane == 0) { ws[wid] = s; wq[wid] = sq; }
    __syncthreads();
    float ts = ws[0] + ws[1] + ws[2] + ws[3];
    float tq = wq[0] + wq[1] + wq[2] + wq[3];
    const float mean = ts * (1.f / 512.f);
    const float var  = tq * (1.f / 512.f) - mean * mean;
    const float rstd = rsqrtf(var + 1e-5f);

    float4 gv = *(const float4*)&g[tid * 4];
    float4 bv = *(const float4*)&beta[tid * 4];
    float4 o;
    o.x = (v.x - mean) * rstd * gv.x + bv.x;
    o.y = (v.y - mean) * rstd * gv.y + bv.y;
    o.z = (v.z - mean) * rstd * gv.z + bv.z;
    o.w = (v.w - mean) * rstd * gv.w + bv.w;
    if (roundOut) {
        o.x = round_tf(o.x); o.y = round_tf(o.y);
        o.z = round_tf(o.z); o.w = round_tf(o.w);
    }
    *(float4*)&Y[(size_t)row * 512 + tid * 4] = o;
}

// ---------------- launch ----------------
extern "C" void kernel_launch(void* const* d_in, const int* in_sizes, int n_in,
                              void* d_out, int out_size)
{
    const float* Q   = (const float*)d_in[0];
    const float* K   = (const float*)d_in[1];
    const float* Wq  = (const float*)d_in[2];
    const float* bq  = (const float*)d_in[3];
    const float* Wk  = (const float*)d_in[4];
    const float* bk  = (const float*)d_in[5];
    const float* Wv  = (const float*)d_in[6];
    const float* bv  = (const float*)d_in[7];
    const float* Wo  = (const float*)d_in[8];
    const float* bo  = (const float*)d_in[9];
    const float* g0  = (const float*)d_in[10];
    const float* be0 = (const float*)d_in[11];
    const float* g1  = (const float*)d_in[12];
    const float* be1 = (const float*)d_in[13];
    float* out = (float*)d_out;

    float *Qp, *Kp, *Obuf, *Xbuf, *Tbuf;
    __half* Vth;
    cudaGetSymbolAddress((void**)&Qp,   g_Qp);
    cudaGetSymbolAddress((void**)&Kp,   g_Kp);
    cudaGetSymbolAddress((void**)&Vth,  g_Vth);
    cudaGetSymbolAddress((void**)&Obuf, g_O);
    cudaGetSymbolAddress((void**)&Xbuf, g_X);
    cudaGetSymbolAddress((void**)&Tbuf, g_T);

    cudaFuncSetAttribute(gemm_proj, cudaFuncAttributeMaxDynamicSharedMemorySize, GEMM_SMEM);
    cudaFuncSetAttribute(gemm_out,  cudaFuncAttributeMaxDynamicSharedMemorySize, GEMM_SMEM);
    cudaFuncSetAttribute(attn_fa,   cudaFuncAttributeMaxDynamicSharedMemorySize, ATT_SMEM);

    PArgs pa;
    pa.A[0] = Q;  pa.A[1] = K;  pa.A[2] = K;
    pa.W[0] = Wq; pa.W[1] = Wk; pa.W[2] = Wv;
    pa.b[0] = bq; pa.b[1] = bk; pa.b[2] = bv;
    pa.C[0] = Qp; pa.C[1] = Kp; pa.C[2] = Vth;

    gemm_proj<<<dim3(DV / 64, NROWS / 128, 3), 256, GEMM_SMEM>>>(pa);

    dim3 adim(8, 8, 8);                 // (q-tiles of 128, heads, batch)
    attn_fa<<<adim, 256, ATT_SMEM>>>(Qp, Kp, Vth, Obuf);

    ln512_kernel<<<NROWS, 128>>>(Obuf, g0, be0, Xbuf, 1);
    gemm_out<<<dim3(DV / 64, NROWS / 128), 256, GEMM_SMEM>>>(Xbuf, Wo, bo, Tbuf);
    ln512_kernel<<<NROWS, 128>>>(Tbuf, g1, be1, out, 0);
}

// round 11
// speedup vs baseline: 1.4264x; 1.1254x over previous
#include <cuda_runtime.h>
#include <cuda_fp16.h>
#include <math.h>
#include <stdint.h>

// ---------------- scratch ----------------
#define NROWS 8192
#define DV    512
__device__ float  g_Qp [NROWS * DV];
__device__ float  g_Kp [NROWS * DV];
__device__ __half g_Vth[NROWS * DV];   // V projected, half, transposed: [b][h][d(64)][key(1024)]
__device__ float  g_O  [NROWS * DV];
__device__ float  g_X  [NROWS * DV];
__device__ float  g_T  [NROWS * DV];

// ---------------- helpers ----------------
__device__ __forceinline__ unsigned f2tf(float x) {
    unsigned r; asm("cvt.rna.tf32.f32 %0, %1;" : "=r"(r) : "f"(x)); return r;
}
__device__ __forceinline__ float round_tf(float x) { return __uint_as_float(f2tf(x)); }
__device__ __forceinline__ unsigned packh2(float lo, float hi) {
    __half2 h = __floats2half2_rn(lo, hi);
    return *reinterpret_cast<unsigned*>(&h);
}
__device__ __forceinline__ void mma8(float* d, const unsigned* a, const unsigned* b) {
    asm volatile(
        "mma.sync.aligned.m16n8k8.row.col.f32.tf32.tf32.f32 "
        "{%0,%1,%2,%3},{%4,%5,%6,%7},{%8,%9},{%0,%1,%2,%3};"
        : "+f"(d[0]), "+f"(d[1]), "+f"(d[2]), "+f"(d[3])
        : "r"(a[0]), "r"(a[1]), "r"(a[2]), "r"(a[3]), "r"(b[0]), "r"(b[1]));
}
__device__ __forceinline__ void mmah16(float* d, const unsigned* a, const unsigned* b) {
    asm volatile(
        "mma.sync.aligned.m16n8k16.row.col.f32.f16.f16.f32 "
        "{%0,%1,%2,%3},{%4,%5,%6,%7},{%8,%9},{%0,%1,%2,%3};"
        : "+f"(d[0]), "+f"(d[1]), "+f"(d[2]), "+f"(d[3])
        : "r"(a[0]), "r"(a[1]), "r"(a[2]), "r"(a[3]), "r"(b[0]), "r"(b[1]));
}
__device__ __forceinline__ void ldsm4(unsigned& r0, unsigned& r1, unsigned& r2, unsigned& r3,
                                      uint32_t addr) {
    asm volatile("ldmatrix.sync.aligned.m8n8.x4.shared.b16 {%0,%1,%2,%3}, [%4];"
                 : "=r"(r0), "=r"(r1), "=r"(r2), "=r"(r3) : "r"(addr));
}
__device__ __forceinline__ void cpa16(uint32_t s, const void* g) {
    asm volatile("cp.async.cg.shared.global [%0], [%1], 16;" :: "r"(s), "l"(g));
}
#define CPA_COMMIT() asm volatile("cp.async.commit_group;")
#define CPA_WAIT(n)  asm volatile("cp.async.wait_group %0;" :: "n"(n))

// ---------------- tf32 GEMM core: 128x128 tile, BK=32/stage, 2-stage cp.async ----------------
// C = A[8192,512] @ W[512,512]^T + bias. mode 0: rna-rounded store; 1: relu+residual(A);
// 2: half store, transposed Vt layout.
// 256 threads = 8 warps as 4(m) x 2(n); warp tile 32x64. 16 iterations (half the barriers of BK16).
#define GP 36                        // floats per row (144 B: 16B-aligned, bank-quad distinct)
#define GSTG (2 * 128 * GP)          // floats per stage (A 128 rows + B 128 rows)
#define GEMM_SMEM (2 * GSTG * 4)     // 73728 B -> 3 CTAs/SM by smem

__device__ __forceinline__ void gemm_core(const float* __restrict__ A,
                                          const float* __restrict__ W,
                                          const float* __restrict__ bias,
                                          void* Cv, int mode, float* gsm)
{
    const int tid  = threadIdx.x;
    const int lane = tid & 31;
    const int warp = tid >> 5;
    const int wm = warp & 3;
    const int wn = warp >> 2;
    const int bm = blockIdx.y * 128;
    const int bn = blockIdx.x * 128;
    const int g4 = lane >> 2;
    const int t4 = lane & 3;
    const int i8 = lane & 7;
    const int K = 512, N = 512;

    const uint32_t gsu = (uint32_t)__cvta_generic_to_shared(gsm);
    const uint32_t obA = (uint32_t)(((wm * 32 + ((lane >> 3) & 1) * 8 + i8) * GP
                                     + (lane >> 4) * 4) * 4);
    const uint32_t obB = (uint32_t)((128 * GP + (wn * 64 + (lane >> 4) * 8 + i8) * GP
                                     + ((lane >> 3) & 1) * 4) * 4);

    float acc[2][8][4];
#pragma unroll
    for (int mi = 0; mi < 2; mi++)
#pragma unroll
        for (int ni = 0; ni < 8; ni++)
#pragma unroll
            for (int j = 0; j < 4; j++) acc[mi][ni][j] = 0.f;

    auto issue = [&](int it) {
        float* Adst = gsm + (it & 1) * GSTG;
        float* Bdst = Adst + 128 * GP;
        const int k0 = it * 32;
#pragma unroll
        for (int i = 0; i < 4; i++) {           // A: 128 rows x 32 f32 = 1024 16B chunks
            const int cid = i * 256 + tid;
            const int row = cid >> 3;
            const int c4  = (cid & 7) * 4;
            cpa16((uint32_t)__cvta_generic_to_shared(Adst + row * GP + c4),
                  &A[(size_t)(bm + row) * K + k0 + c4]);
        }
#pragma unroll
        for (int i = 0; i < 4; i++) {           // B: 128 rows x 32 f32
            const int cid = i * 256 + tid;
            const int row = cid >> 3;
            const int c4  = (cid & 7) * 4;
            cpa16((uint32_t)__cvta_generic_to_shared(Bdst + row * GP + c4),
                  &W[(size_t)(bn + row) * K + k0 + c4]);
        }
    };

    const int NIT = 16;   // K=512, BK=32
    issue(0); CPA_COMMIT();

    for (int it = 0; it < NIT; it++) {
        if (it + 1 < NIT) { issue(it + 1); CPA_COMMIT(); CPA_WAIT(1); }
        else              { CPA_WAIT(0); }
        __syncthreads();

        const uint32_t sb = gsu + (uint32_t)((it & 1) * GSTG * 4);
#pragma unroll
        for (int ks = 0; ks < 4; ks++) {
            unsigned af[2][4];
#pragma unroll
            for (int mi = 0; mi < 2; mi++)
                ldsm4(af[mi][0], af[mi][1], af[mi][2], af[mi][3],
                      sb + obA + (uint32_t)((mi * 16 * GP + ks * 8) * 4));
#pragma unroll
            for (int n2 = 0; n2 < 4; n2++) {
                unsigned b0, b1, b2, b3;
                ldsm4(b0, b1, b2, b3, sb + obB + (uint32_t)((n2 * 16 * GP + ks * 8) * 4));
                unsigned be[2] = {b0, b1}, bo_[2] = {b2, b3};
                mma8(acc[0][n2 * 2],     af[0], be);
                mma8(acc[1][n2 * 2],     af[1], be);
                mma8(acc[0][n2 * 2 + 1], af[0], bo_);
                mma8(acc[1][n2 * 2 + 1], af[1], bo_);
            }
        }
        __syncthreads();
    }

#pragma unroll
    for (int mi = 0; mi < 2; mi++) {
#pragma unroll
        for (int ni = 0; ni < 8; ni++) {
            const int row = bm + wm * 32 + mi * 16 + g4;
            const int col = bn + wn * 64 + ni * 8 + 2 * t4;
            const float b0 = bias[col], b1 = bias[col + 1];
            float v00 = acc[mi][ni][0] + b0, v01 = acc[mi][ni][1] + b1;
            float v10 = acc[mi][ni][2] + b0, v11 = acc[mi][ni][3] + b1;
            if (mode == 2) {
                // half store, transposed: Vt[((b*8+h)*64+d)*1024 + key]
                const int b_ = row >> 10, key = row & 1023;
                const int h_ = col >> 6, d_ = col & 63;
                __half* base = (__half*)Cv + (((size_t)(b_ * 8 + h_) * 64 + d_) << 10);
                base[key]            = __float2half(v00);
                base[1024 + key]     = __float2half(v01);
                base[key + 8]        = __float2half(v10);
                base[1024 + key + 8] = __float2half(v11);
            } else {
                if (mode == 1) {
                    v00 = fmaxf(v00, 0.f) + A[(size_t)row * K + col];
                    v01 = fmaxf(v01, 0.f) + A[(size_t)row * K + col + 1];
                    v10 = fmaxf(v10, 0.f) + A[(size_t)(row + 8) * K + col];
                    v11 = fmaxf(v11, 0.f) + A[(size_t)(row + 8) * K + col + 1];
                } else {
                    v00 = round_tf(v00); v01 = round_tf(v01);
                    v10 = round_tf(v10); v11 = round_tf(v11);
                }
                float* C = (float*)Cv;
                *(float2*)&C[(size_t)row * N + col]       = make_float2(v00, v01);
                *(float2*)&C[(size_t)(row + 8) * N + col] = make_float2(v10, v11);
            }
        }
    }
}

struct PArgs {
    const float* A[3]; const float* W[3]; const float* b[3]; void* C[3];
};

__global__ __launch_bounds__(256) void gemm_proj(PArgs pa) {
    extern __shared__ float gsm[];
    const int z = blockIdx.z;
    gemm_core(pa.A[z], pa.W[z], pa.b[z], pa.C[z], (z == 2) ? 2 : 0, gsm);
}
__global__ __launch_bounds__(256) void gemm_out(const float* __restrict__ A,
                                                const float* __restrict__ W,
                                                const float* __restrict__ b, float* C) {
    extern __shared__ float gsm[];
    gemm_core(A, W, b, C, 1, gsm);
}

// ---------------- flash attention: tf32 S + f16 PV (FA2 fragment reuse), 4-stage cp.async ----------------
// 256 threads = 8 warps; block = (128 q-rows, head, batch); warp owns 16 q rows.
#define KSTR 68   // K tile stride (floats)
#define VSTR 72   // V tile stride (halves) -> 144B rows, conflict-free ldmatrix
#define ATT_SMEM (4 * 64 * KSTR * 4 + 4 * 64 * VSTR * 2)   // 106496 B

__global__ __launch_bounds__(256, 2)
void attn_fa(const float* __restrict__ Qp, const float* __restrict__ Kp,
             const __half* __restrict__ Vth, float* __restrict__ O)
{
    extern __shared__ __align__(16) float dsm[];
    float*  Kst = dsm;                                 // 4 stages x [64][KSTR] f32
    __half* Vst = (__half*)(dsm + 4 * 64 * KSTR);      // 4 stages x [64][VSTR] f16

    const int tid  = threadIdx.x;
    const int lane = tid & 31;
    const int warp = tid >> 5;
    const int g4 = lane >> 2;
    const int t4 = lane & 3;
    const int i8 = lane & 7;

    const int qt = blockIdx.x, h = blockIdx.y, b = blockIdx.z;
    const int q0 = qt * 128;
    const size_t gbase  = ((size_t)b * 1024) * 512 + (size_t)h * 64;
    const size_t vtbase = ((size_t)(b * 8 + h)) << 16;   // halves: *64*1024
    const float scale = 0.044194173824159216f;  // 1/sqrt(512)

    // lane constants
    const uint32_t obB = (uint32_t)((((lane >> 4) * 8 + i8) * KSTR + ((lane >> 3) & 1) * 4) * 4);
    const uint32_t vlane = (uint32_t)(((((lane >> 4) & 1) * 8 + i8) * VSTR
                                      + ((lane >> 3) & 1) * 8) * 2);
    const uint32_t ku0 = (uint32_t)__cvta_generic_to_shared(Kst);
    const uint32_t vu0 = (uint32_t)__cvta_generic_to_shared(Vst);

    auto issue = [&](int kt) {
        const int st = kt & 3;
        float*  kd = Kst + st * 64 * KSTR;
        __half* vd = Vst + st * 64 * VSTR;
#pragma unroll
        for (int i = 0; i < 4; i++) {   // K: 64 rows x 64 f32
            const int cid = i * 256 + tid;
            const int row = cid >> 4;
            const int c4  = (cid & 15) * 4;
            cpa16((uint32_t)__cvta_generic_to_shared(kd + row * KSTR + c4),
                  Kp + gbase + (size_t)(kt * 64 + row) * 512 + c4);
        }
#pragma unroll
        for (int i = 0; i < 2; i++) {   // V: 64 rows(d) x 64 halves
            const int cid = i * 256 + tid;
            const int row = cid >> 3;
            const int c8  = (cid & 7) * 8;
            cpa16((uint32_t)__cvta_generic_to_shared(vd + row * VSTR + c8),
                  Vth + vtbase + (size_t)row * 1024 + kt * 64 + c8);
        }
    };

    // Q fragments (rna tf32, pre-scaled), register-resident
    const int qr = q0 + warp * 16 + g4;
    const float* Qrow0 = Qp + gbase + (size_t)qr * 512;
    const float* Qrow1 = Qrow0 + (size_t)8 * 512;
    unsigned aq[8][4];
#pragma unroll
    for (int ks = 0; ks < 8; ks++) {
        const int c = ks * 8 + t4;
        aq[ks][0] = f2tf(Qrow0[c] * scale);
        aq[ks][1] = f2tf(Qrow1[c] * scale);
        aq[ks][2] = f2tf(Qrow0[c + 4] * scale);
        aq[ks][3] = f2tf(Qrow1[c + 4] * scale);
    }

    float l0 = 0.f, l1 = 0.f;
    float o[8][4];
#pragma unroll
    for (int ni = 0; ni < 8; ni++)
#pragma unroll
        for (int j = 0; j < 4; j++) o[ni][j] = 0.f;

    issue(0); CPA_COMMIT();
    issue(1); CPA_COMMIT();
    issue(2); CPA_COMMIT();

    for (int kt = 0; kt < 16; kt++) {
        if (kt + 3 < 16) issue(kt + 3);
        CPA_COMMIT();
        CPA_WAIT(3);
        __syncthreads();

        const uint32_t ku = ku0 + (uint32_t)((kt & 3) * 64 * KSTR * 4);
        const uint32_t vu = vu0 + (uint32_t)((kt & 3) * 64 * VSTR * 2);

        // S = Qs @ K^T (16 rows x 64 keys per warp), tf32
        float s[8][4];
#pragma unroll
        for (int ni = 0; ni < 8; ni++)
#pragma unroll
            for (int j = 0; j < 4; j++) s[ni][j] = 0.f;

#pragma unroll
        for (int ks = 0; ks < 8; ks++) {
#pragma unroll
            for (int n2 = 0; n2 < 4; n2++) {
                unsigned b0, b1, b2, b3;
                ldsm4(b0, b1, b2, b3, ku + obB + (uint32_t)((n2 * 16 * KSTR + ks * 8) * 4));
                unsigned be[2] = {b0, b1}, bo_[2] = {b2, b3};
                mma8(s[n2 * 2],     aq[ks], be);
                mma8(s[n2 * 2 + 1], aq[ks], bo_);
            }
        }

        // softmax without max subtraction (scores bounded; clamp for safety).
        // partial l per thread (its 16 keys); reduced across t4 lanes after the loop.
#pragma unroll
        for (int ni = 0; ni < 8; ni++) {
            s[ni][0] = __expf(fminf(s[ni][0], 60.f));
            s[ni][1] = __expf(fminf(s[ni][1], 60.f));
            s[ni][2] = __expf(fminf(s[ni][2], 60.f));
            s[ni][3] = __expf(fminf(s[ni][3], 60.f));
            l0 += s[ni][0] + s[ni][1];
            l1 += s[ni][2] + s[ni][3];
        }

        // O += P @ V : P converted f32->f16 IN REGISTERS (C-fragment == f16 A-fragment),
        // V (half, [d][key]) B-fragments via ldmatrix. m16n8k16.
#pragma unroll
        for (int c = 0; c < 4; c++) {
            unsigned ap[4];
            ap[0] = packh2(s[2 * c][0],     s[2 * c][1]);      // row g4,   k 2t4..
            ap[1] = packh2(s[2 * c][2],     s[2 * c][3]);      // row g4+8
            ap[2] = packh2(s[2 * c + 1][0], s[2 * c + 1][1]);  // row g4,   k 2t4+8..
            ap[3] = packh2(s[2 * c + 1][2], s[2 * c + 1][3]);  // row g4+8
#pragma unroll
            for (int n2 = 0; n2 < 4; n2++) {
                unsigned b0, b1, b2, b3;
                ldsm4(b0, b1, b2, b3,
                      vu + vlane + (uint32_t)(((n2 * 16) * VSTR + c * 16) * 2));
                unsigned be[2] = {b0, b1}, bo_[2] = {b2, b3};
                mmah16(o[n2 * 2],     ap, be);
                mmah16(o[n2 * 2 + 1], ap, bo_);
            }
        }
        __syncthreads();
    }

    // reduce softmax denominators across the 4 t4-lanes (full 1024-key sums)
    l0 += __shfl_xor_sync(0xffffffffu, l0, 1);
    l0 += __shfl_xor_sync(0xffffffffu, l0, 2);
    l1 += __shfl_xor_sync(0xffffffffu, l1, 1);
    l1 += __shfl_xor_sync(0xffffffffu, l1, 2);

    // epilogue: normalize + Q residual
    const float inv0 = 1.f / l0, inv1 = 1.f / l1;
    float* Ob = O + gbase + (size_t)qr * 512;
#pragma unroll
    for (int ni = 0; ni < 8; ni++) {
        const int col = ni * 8 + 2 * t4;
        float2 r0 = make_float2(o[ni][0] * inv0 + Qrow0[col],
                                o[ni][1] * inv0 + Qrow0[col + 1]);
        float2 r1 = make_float2(o[ni][2] * inv1 + Qrow1[col],
                                o[ni][3] * inv1 + Qrow1[col + 1]);
        *(float2*)&Ob[col]                   = r0;
        *(float2*)&Ob[(size_t)8 * 512 + col] = r1;
    }
}

// ---------------- layernorm over 512 features ----------------
__global__ __launch_bounds__(128)
void ln512_kernel(const float* __restrict__ X, const float* __restrict__ g,
                  const float* __restrict__ beta, float* __restrict__ Y, int roundOut)
{
    const int row = blockIdx.x;
    const int tid = threadIdx.x;
    const int lane = tid & 31;
    const int wid = tid >> 5;

    float4 v = *(const float4*)&X[(size_t)row * 512 + tid * 4];
    float s  = v.x + v.y + v.z + v.w;
    float sq = v.x * v.x + v.y * v.y + v.z * v.z + v.w * v.w;
#pragma unroll
    for (int o = 16; o; o >>= 1) {
        s  += __shfl_xor_sync(0xffffffffu, s, o);
        sq += __shfl_xor_sync(0xffffffffu, sq, o);
    }
    __shared__ float ws[4], wq[4];
    if (lane == 0) { ws[wid] = s; wq[wid] = sq; }
    __syncthreads();
    float ts = ws[0] + ws[1] + ws[2] + ws[3];
    float tq = wq[0] + wq[1] + wq[2] + wq[3];
    const float mean = ts * (1.f / 512.f);
    const float var  = tq * (1.f / 512.f) - mean * mean;
    const float rstd = rsqrtf(var + 1e-5f);

    float4 gv = *(const float4*)&g[tid * 4];
    float4 bv = *(const float4*)&beta[tid * 4];
    float4 o;
    o.x = (v.x - mean) * rstd * gv.x + bv.x;
    o.y = (v.y - mean) * rstd * gv.y + bv.y;
    o.z = (v.z - mean) * rstd * gv.z + bv.z;
    o.w = (v.w - mean) * rstd * gv.w + bv.w;
    if (roundOut) {
        o.x = round_tf(o.x); o.y = round_tf(o.y);
        o.z = round_tf(o.z); o.w = round_tf(o.w);
    }
    *(float4*)&Y[(size_t)row * 512 + tid * 4] = o;
}

// ---------------- launch ----------------
extern "C" void kernel_launch(void* const* d_in, const int* in_sizes, int n_in,
                              void* d_out, int out_size)
{
    const float* Q   = (const float*)d_in[0];
    const float* K   = (const float*)d_in[1];
    const float* Wq  = (const float*)d_in[2];
    const float* bq  = (const float*)d_in[3];
    const float* Wk  = (const float*)d_in[4];
    const float* bk  = (const float*)d_in[5];
    const float* Wv  = (const float*)d_in[6];
    const float* bv  = (const float*)d_in[7];
    const float* Wo  = (const float*)d_in[8];
    const float* bo  = (const float*)d_in[9];
    const float* g0  = (const float*)d_in[10];
    const float* be0 = (const float*)d_in[11];
    const float* g1  = (const float*)d_in[12];
    const float* be1 = (const float*)d_in[13];
    float* out = (float*)d_out;

    float *Qp, *Kp, *Obuf, *Xbuf, *Tbuf;
    __half* Vth;
    cudaGetSymbolAddress((void**)&Qp,   g_Qp);
    cudaGetSymbolAddress((void**)&Kp,   g_Kp);
    cudaGetSymbolAddress((void**)&Vth,  g_Vth);
    cudaGetSymbolAddress((void**)&Obuf, g_O);
    cudaGetSymbolAddress((void**)&Xbuf, g_X);
    cudaGetSymbolAddress((void**)&Tbuf, g_T);

    cudaFuncSetAttribute(gemm_proj, cudaFuncAttributeMaxDynamicSharedMemorySize, GEMM_SMEM);
    cudaFuncSetAttribute(gemm_out,  cudaFuncAttributeMaxDynamicSharedMemorySize, GEMM_SMEM);
    cudaFuncSetAttribute(attn_fa,   cudaFuncAttributeMaxDynamicSharedMemorySize, ATT_SMEM);

    PArgs pa;
    pa.A[0] = Q;  pa.A[1] = K;  pa.A[2] = K;
    pa.W[0] = Wq; pa.W[1] = Wk; pa.W[2] = Wv;
    pa.b[0] = bq; pa.b[1] = bk; pa.b[2] = bv;
    pa.C[0] = Qp; pa.C[1] = Kp; pa.C[2] = Vth;

    gemm_proj<<<dim3(DV / 128, NROWS / 128, 3), 256, GEMM_SMEM>>>(pa);

    dim3 adim(8, 8, 8);                 // (q-tiles of 128, heads, batch)
    attn_fa<<<adim, 256, ATT_SMEM>>>(Qp, Kp, Vth, Obuf);

    ln512_kernel<<<NROWS, 128>>>(Obuf, g0, be0, Xbuf, 1);
    gemm_out<<<dim3(DV / 128, NROWS / 128), 256, GEMM_SMEM>>>(Xbuf, Wo, bo, Tbuf);
    ln512_kernel<<<NROWS, 128>>>(Tbuf, g1, be1, out, 0);
}

// round 12
// speedup vs baseline: 1.5489x; 1.0859x over previous
#include <cuda_runtime.h>
#include <cuda_fp16.h>
#include <math.h>
#include <stdint.h>

// ---------------- scratch ----------------
#define NROWS 8192
#define DV    512
__device__ float  g_Qp [NROWS * DV];
__device__ float  g_Kp [NROWS * DV];
__device__ __half g_Vth[NROWS * DV];   // V projected, half, transposed: [b][h][d(64)][key(1024)]
__device__ float  g_O  [NROWS * DV];
__device__ float  g_X  [NROWS * DV];
__device__ float  g_T  [NROWS * DV];

// ---------------- helpers ----------------
__device__ __forceinline__ unsigned f2tf(float x) {
    unsigned r; asm("cvt.rna.tf32.f32 %0, %1;" : "=r"(r) : "f"(x)); return r;
}
__device__ __forceinline__ float round_tf(float x) { return __uint_as_float(f2tf(x)); }
__device__ __forceinline__ unsigned packh2(float lo, float hi) {
    __half2 h = __floats2half2_rn(lo, hi);
    return *reinterpret_cast<unsigned*>(&h);
}
__device__ __forceinline__ void mma8(float* d, const unsigned* a, const unsigned* b) {
    asm volatile(
        "mma.sync.aligned.m16n8k8.row.col.f32.tf32.tf32.f32 "
        "{%0,%1,%2,%3},{%4,%5,%6,%7},{%8,%9},{%0,%1,%2,%3};"
        : "+f"(d[0]), "+f"(d[1]), "+f"(d[2]), "+f"(d[3])
        : "r"(a[0]), "r"(a[1]), "r"(a[2]), "r"(a[3]), "r"(b[0]), "r"(b[1]));
}
__device__ __forceinline__ void mmah16(float* d, const unsigned* a, const unsigned* b) {
    asm volatile(
        "mma.sync.aligned.m16n8k16.row.col.f32.f16.f16.f32 "
        "{%0,%1,%2,%3},{%4,%5,%6,%7},{%8,%9},{%0,%1,%2,%3};"
        : "+f"(d[0]), "+f"(d[1]), "+f"(d[2]), "+f"(d[3])
        : "r"(a[0]), "r"(a[1]), "r"(a[2]), "r"(a[3]), "r"(b[0]), "r"(b[1]));
}
__device__ __forceinline__ void ldsm4(unsigned& r0, unsigned& r1, unsigned& r2, unsigned& r3,
                                      uint32_t addr) {
    asm volatile("ldmatrix.sync.aligned.m8n8.x4.shared.b16 {%0,%1,%2,%3}, [%4];"
                 : "=r"(r0), "=r"(r1), "=r"(r2), "=r"(r3) : "r"(addr));
}
__device__ __forceinline__ void cpa16(uint32_t s, const void* g) {
    asm volatile("cp.async.cg.shared.global [%0], [%1], 16;" :: "r"(s), "l"(g));
}
#define CPA_COMMIT() asm volatile("cp.async.commit_group;")
#define CPA_WAIT(n)  asm volatile("cp.async.wait_group %0;" :: "n"(n))

// ---------------- tf32 GEMM core: 128x128 tile, BK=32, 3-stage, ONE sync/iter ----------------
// C = A[8192,512] @ W[512,512]^T + bias. mode 0: rna-rounded store; 1: relu+residual(A);
// 2: half store, transposed Vt layout.
// Single barrier per iteration: issue(it+2) after compute targets stage (it-1)%3 whose
// readers are already past this iteration's top barrier.
#define GP 36                        // floats per row (144 B: 16B-aligned, bank-quad distinct)
#define GSTG (2 * 128 * GP)          // floats per stage (A 128 rows + B 128 rows)
#define GEMM_SMEM (3 * GSTG * 4)     // 110592 B -> 2 CTAs/SM

__device__ __forceinline__ void gemm_core(const float* __restrict__ A,
                                          const float* __restrict__ W,
                                          const float* __restrict__ bias,
                                          void* Cv, int mode, float* gsm)
{
    const int tid  = threadIdx.x;
    const int lane = tid & 31;
    const int warp = tid >> 5;
    const int wm = warp & 3;
    const int wn = warp >> 2;
    const int bm = blockIdx.y * 128;
    const int bn = blockIdx.x * 128;
    const int g4 = lane >> 2;
    const int t4 = lane & 3;
    const int i8 = lane & 7;
    const int K = 512, N = 512;

    const uint32_t gsu = (uint32_t)__cvta_generic_to_shared(gsm);
    const uint32_t obA = (uint32_t)(((wm * 32 + ((lane >> 3) & 1) * 8 + i8) * GP
                                     + (lane >> 4) * 4) * 4);
    const uint32_t obB = (uint32_t)((128 * GP + (wn * 64 + (lane >> 4) * 8 + i8) * GP
                                     + ((lane >> 3) & 1) * 4) * 4);

    float acc[2][8][4];
#pragma unroll
    for (int mi = 0; mi < 2; mi++)
#pragma unroll
        for (int ni = 0; ni < 8; ni++)
#pragma unroll
            for (int j = 0; j < 4; j++) acc[mi][ni][j] = 0.f;

    auto issue = [&](int it) {
        float* Adst = gsm + (it % 3) * GSTG;
        float* Bdst = Adst + 128 * GP;
        const int k0 = it * 32;
#pragma unroll
        for (int i = 0; i < 4; i++) {           // A: 128 rows x 32 f32
            const int cid = i * 256 + tid;
            const int row = cid >> 3;
            const int c4  = (cid & 7) * 4;
            cpa16((uint32_t)__cvta_generic_to_shared(Adst + row * GP + c4),
                  &A[(size_t)(bm + row) * K + k0 + c4]);
        }
#pragma unroll
        for (int i = 0; i < 4; i++) {           // B: 128 rows x 32 f32
            const int cid = i * 256 + tid;
            const int row = cid >> 3;
            const int c4  = (cid & 7) * 4;
            cpa16((uint32_t)__cvta_generic_to_shared(Bdst + row * GP + c4),
                  &W[(size_t)(bn + row) * K + k0 + c4]);
        }
    };

    const int NIT = 16;   // K=512, BK=32
    issue(0); CPA_COMMIT();
    issue(1); CPA_COMMIT();

    for (int it = 0; it < NIT; it++) {
        CPA_WAIT(1);
        __syncthreads();

        const uint32_t sb = gsu + (uint32_t)((it % 3) * GSTG * 4);
#pragma unroll
        for (int ks = 0; ks < 4; ks++) {
            unsigned af[2][4];
#pragma unroll
            for (int mi = 0; mi < 2; mi++)
                ldsm4(af[mi][0], af[mi][1], af[mi][2], af[mi][3],
                      sb + obA + (uint32_t)((mi * 16 * GP + ks * 8) * 4));
#pragma unroll
            for (int n2 = 0; n2 < 4; n2++) {
                unsigned b0, b1, b2, b3;
                ldsm4(b0, b1, b2, b3, sb + obB + (uint32_t)((n2 * 16 * GP + ks * 8) * 4));
                unsigned be[2] = {b0, b1}, bo_[2] = {b2, b3};
                mma8(acc[0][n2 * 2],     af[0], be);
                mma8(acc[1][n2 * 2],     af[1], be);
                mma8(acc[0][n2 * 2 + 1], af[0], bo_);
                mma8(acc[1][n2 * 2 + 1], af[1], bo_);
            }
        }

        if (it + 2 < NIT) issue(it + 2);
        CPA_COMMIT();   // empty groups in the tail keep wait-depth semantics constant
    }

#pragma unroll
    for (int mi = 0; mi < 2; mi++) {
#pragma unroll
        for (int ni = 0; ni < 8; ni++) {
            const int row = bm + wm * 32 + mi * 16 + g4;
            const int col = bn + wn * 64 + ni * 8 + 2 * t4;
            const float b0 = bias[col], b1 = bias[col + 1];
            float v00 = acc[mi][ni][0] + b0, v01 = acc[mi][ni][1] + b1;
            float v10 = acc[mi][ni][2] + b0, v11 = acc[mi][ni][3] + b1;
            if (mode == 2) {
                // half store, transposed: Vt[((b*8+h)*64+d)*1024 + key]
                const int b_ = row >> 10, key = row & 1023;
                const int h_ = col >> 6, d_ = col & 63;
                __half* base = (__half*)Cv + (((size_t)(b_ * 8 + h_) * 64 + d_) << 10);
                base[key]            = __float2half(v00);
                base[1024 + key]     = __float2half(v01);
                base[key + 8]        = __float2half(v10);
                base[1024 + key + 8] = __float2half(v11);
            } else {
                if (mode == 1) {
                    v00 = fmaxf(v00, 0.f) + A[(size_t)row * K + col];
                    v01 = fmaxf(v01, 0.f) + A[(size_t)row * K + col + 1];
                    v10 = fmaxf(v10, 0.f) + A[(size_t)(row + 8) * K + col];
                    v11 = fmaxf(v11, 0.f) + A[(size_t)(row + 8) * K + col + 1];
                } else {
                    v00 = round_tf(v00); v01 = round_tf(v01);
                    v10 = round_tf(v10); v11 = round_tf(v11);
                }
                float* C = (float*)Cv;
                *(float2*)&C[(size_t)row * N + col]       = make_float2(v00, v01);
                *(float2*)&C[(size_t)(row + 8) * N + col] = make_float2(v10, v11);
            }
        }
    }
}

struct PArgs {
    const float* A[3]; const float* W[3]; const float* b[3]; void* C[3];
};

__global__ __launch_bounds__(256) void gemm_proj(PArgs pa) {
    extern __shared__ float gsm[];
    const int z = blockIdx.z;
    gemm_core(pa.A[z], pa.W[z], pa.b[z], pa.C[z], (z == 2) ? 2 : 0, gsm);
}
__global__ __launch_bounds__(256) void gemm_out(const float* __restrict__ A,
                                                const float* __restrict__ W,
                                                const float* __restrict__ b, float* C) {
    extern __shared__ float gsm[];
    gemm_core(A, W, b, C, 1, gsm);
}

// ---------------- flash attention: tf32 S + f16 PV, 4-stage cp.async, ONE sync/iter ----------------
// 256 threads = 8 warps; block = (128 q-rows, head, batch); warp owns 16 q rows.
// issue(kt+3) after compute targets stage (kt-1)&3 whose readers are past this iter's barrier.
#define KSTR 68   // K tile stride (floats)
#define VSTR 72   // V tile stride (halves) -> 144B rows, conflict-free ldmatrix
#define ATT_SMEM (4 * 64 * KSTR * 4 + 4 * 64 * VSTR * 2)   // 106496 B

__global__ __launch_bounds__(256, 2)
void attn_fa(const float* __restrict__ Qp, const float* __restrict__ Kp,
             const __half* __restrict__ Vth, float* __restrict__ O)
{
    extern __shared__ __align__(16) float dsm[];
    float*  Kst = dsm;                                 // 4 stages x [64][KSTR] f32
    __half* Vst = (__half*)(dsm + 4 * 64 * KSTR);      // 4 stages x [64][VSTR] f16

    const int tid  = threadIdx.x;
    const int lane = tid & 31;
    const int warp = tid >> 5;
    const int g4 = lane >> 2;
    const int t4 = lane & 3;
    const int i8 = lane & 7;

    const int qt = blockIdx.x, h = blockIdx.y, b = blockIdx.z;
    const int q0 = qt * 128;
    const size_t gbase  = ((size_t)b * 1024) * 512 + (size_t)h * 64;
    const size_t vtbase = ((size_t)(b * 8 + h)) << 16;   // halves: *64*1024
    const float scale = 0.044194173824159216f;  // 1/sqrt(512)

    // lane constants
    const uint32_t obB = (uint32_t)((((lane >> 4) * 8 + i8) * KSTR + ((lane >> 3) & 1) * 4) * 4);
    const uint32_t vlane = (uint32_t)(((((lane >> 4) & 1) * 8 + i8) * VSTR
                                      + ((lane >> 3) & 1) * 8) * 2);
    const uint32_t ku0 = (uint32_t)__cvta_generic_to_shared(Kst);
    const uint32_t vu0 = (uint32_t)__cvta_generic_to_shared(Vst);

    auto issue = [&](int kt) {
        const int st = kt & 3;
        float*  kd = Kst + st * 64 * KSTR;
        __half* vd = Vst + st * 64 * VSTR;
#pragma unroll
        for (int i = 0; i < 4; i++) {   // K: 64 rows x 64 f32
            const int cid = i * 256 + tid;
            const int row = cid >> 4;
            const int c4  = (cid & 15) * 4;
            cpa16((uint32_t)__cvta_generic_to_shared(kd + row * KSTR + c4),
                  Kp + gbase + (size_t)(kt * 64 + row) * 512 + c4);
        }
#pragma unroll
        for (int i = 0; i < 2; i++) {   // V: 64 rows(d) x 64 halves
            const int cid = i * 256 + tid;
            const int row = cid >> 3;
            const int c8  = (cid & 7) * 8;
            cpa16((uint32_t)__cvta_generic_to_shared(vd + row * VSTR + c8),
                  Vth + vtbase + (size_t)row * 1024 + kt * 64 + c8);
        }
    };

    // Q fragments (rna tf32, pre-scaled), register-resident
    const int qr = q0 + warp * 16 + g4;
    const float* Qrow0 = Qp + gbase + (size_t)qr * 512;
    const float* Qrow1 = Qrow0 + (size_t)8 * 512;
    unsigned aq[8][4];
#pragma unroll
    for (int ks = 0; ks < 8; ks++) {
        const int c = ks * 8 + t4;
        aq[ks][0] = f2tf(Qrow0[c] * scale);
        aq[ks][1] = f2tf(Qrow1[c] * scale);
        aq[ks][2] = f2tf(Qrow0[c + 4] * scale);
        aq[ks][3] = f2tf(Qrow1[c + 4] * scale);
    }

    float l0 = 0.f, l1 = 0.f;
    float o[8][4];
#pragma unroll
    for (int ni = 0; ni < 8; ni++)
#pragma unroll
        for (int j = 0; j < 4; j++) o[ni][j] = 0.f;

    issue(0); CPA_COMMIT();
    issue(1); CPA_COMMIT();
    issue(2); CPA_COMMIT();

    for (int kt = 0; kt < 16; kt++) {
        CPA_WAIT(2);
        __syncthreads();

        const uint32_t ku = ku0 + (uint32_t)((kt & 3) * 64 * KSTR * 4);
        const uint32_t vu = vu0 + (uint32_t)((kt & 3) * 64 * VSTR * 2);

        // S = Qs @ K^T (16 rows x 64 keys per warp), tf32
        float s[8][4];
#pragma unroll
        for (int ni = 0; ni < 8; ni++)
#pragma unroll
            for (int j = 0; j < 4; j++) s[ni][j] = 0.f;

#pragma unroll
        for (int ks = 0; ks < 8; ks++) {
#pragma unroll
            for (int n2 = 0; n2 < 4; n2++) {
                unsigned b0, b1, b2, b3;
                ldsm4(b0, b1, b2, b3, ku + obB + (uint32_t)((n2 * 16 * KSTR + ks * 8) * 4));
                unsigned be[2] = {b0, b1}, bo_[2] = {b2, b3};
                mma8(s[n2 * 2],     aq[ks], be);
                mma8(s[n2 * 2 + 1], aq[ks], bo_);
            }
        }

        // softmax without max subtraction (scores bounded; clamp for safety).
        // partial l per thread (its 16 keys); reduced across t4 lanes after the loop.
#pragma unroll
        for (int ni = 0; ni < 8; ni++) {
            s[ni][0] = __expf(fminf(s[ni][0], 60.f));
            s[ni][1] = __expf(fminf(s[ni][1], 60.f));
            s[ni][2] = __expf(fminf(s[ni][2], 60.f));
            s[ni][3] = __expf(fminf(s[ni][3], 60.f));
            l0 += s[ni][0] + s[ni][1];
            l1 += s[ni][2] + s[ni][3];
        }

        // O += P @ V : P converted f32->f16 IN REGISTERS (C-fragment == f16 A-fragment),
        // V (half, [d][key]) B-fragments via ldmatrix. m16n8k16.
#pragma unroll
        for (int c = 0; c < 4; c++) {
            unsigned ap[4];
            ap[0] = packh2(s[2 * c][0],     s[2 * c][1]);      // row g4,   k 2t4..
            ap[1] = packh2(s[2 * c][2],     s[2 * c][3]);      // row g4+8
            ap[2] = packh2(s[2 * c + 1][0], s[2 * c + 1][1]);  // row g4,   k 2t4+8..
            ap[3] = packh2(s[2 * c + 1][2], s[2 * c + 1][3]);  // row g4+8
#pragma unroll
            for (int n2 = 0; n2 < 4; n2++) {
                unsigned b0, b1, b2, b3;
                ldsm4(b0, b1, b2, b3,
                      vu + vlane + (uint32_t)(((n2 * 16) * VSTR + c * 16) * 2));
                unsigned be[2] = {b0, b1}, bo_[2] = {b2, b3};
                mmah16(o[n2 * 2],     ap, be);
                mmah16(o[n2 * 2 + 1], ap, bo_);
            }
        }

        if (kt + 3 < 16) issue(kt + 3);
        CPA_COMMIT();   // empty groups in the tail keep wait-depth semantics constant
    }

    // reduce softmax denominators across the 4 t4-lanes (full 1024-key sums)
    l0 += __shfl_xor_sync(0xffffffffu, l0, 1);
    l0 += __shfl_xor_sync(0xffffffffu, l0, 2);
    l1 += __shfl_xor_sync(0xffffffffu, l1, 1);
    l1 += __shfl_xor_sync(0xffffffffu, l1, 2);

    // epilogue: normalize + Q residual
    const float inv0 = 1.f / l0, inv1 = 1.f / l1;
    float* Ob = O + gbase + (size_t)qr * 512;
#pragma unroll
    for (int ni = 0; ni < 8; ni++) {
        const int col = ni * 8 + 2 * t4;
        float2 r0 = make_float2(o[ni][0] * inv0 + Qrow0[col],
                                o[ni][1] * inv0 + Qrow0[col + 1]);
        float2 r1 = make_float2(o[ni][2] * inv1 + Qrow1[col],
                                o[ni][3] * inv1 + Qrow1[col + 1]);
        *(float2*)&Ob[col]                   = r0;
        *(float2*)&Ob[(size_t)8 * 512 + col] = r1;
    }
}

// ---------------- layernorm over 512 features ----------------
__global__ __launch_bounds__(128)
void ln512_kernel(const float* __restrict__ X, const float* __restrict__ g,
                  const float* __restrict__ beta, float* __restrict__ Y, int roundOut)
{
    const int row = blockIdx.x;
    const int tid = threadIdx.x;
    const int lane = tid & 31;
    const int wid = tid >> 5;

    float4 v = *(const float4*)&X[(size_t)row * 512 + tid * 4];
    float s  = v.x + v.y + v.z + v.w;
    float sq = v.x * v.x + v.y * v.y + v.z * v.z + v.w * v.w;
#pragma unroll
    for (int o = 16; o; o >>= 1) {
        s  += __shfl_xor_sync(0xffffffffu, s, o);
        sq += __shfl_xor_sync(0xffffffffu, sq, o);
    }
    __shared__ float ws[4], wq[4];
    if (lane == 0) { ws[wid] = s; wq[wid] = sq; }
    __syncthreads();
    float ts = ws[0] + ws[1] + ws[2] + ws[3];
    float tq = wq[0] + wq[1] + wq[2] + wq[3];
    const float mean = ts * (1.f / 512.f);
    const float var  = tq * (1.f / 512.f) - mean * mean;
    const float rstd = rsqrtf(var + 1e-5f);

    float4 gv = *(const float4*)&g[tid * 4];
    float4 bv = *(const float4*)&beta[tid * 4];
    float4 o;
    o.x = (v.x - mean) * rstd * gv.x + bv.x;
    o.y = (v.y - mean) * rstd * gv.y + bv.y;
    o.z = (v.z - mean) * rstd * gv.z + bv.z;
    o.w = (v.w - mean) * rstd * gv.w + bv.w;
    if (roundOut) {
        o.x = round_tf(o.x); o.y = round_tf(o.y);
        o.z = round_tf(o.z); o.w = round_tf(o.w);
    }
    *(float4*)&Y[(size_t)row * 512 + tid * 4] = o;
}

// ---------------- launch ----------------
extern "C" void kernel_launch(void* const* d_in, const int* in_sizes, int n_in,
                              void* d_out, int out_size)
{
    const float* Q   = (const float*)d_in[0];
    const float* K   = (const float*)d_in[1];
    const float* Wq  = (const float*)d_in[2];
    const float* bq  = (const float*)d_in[3];
    const float* Wk  = (const float*)d_in[4];
    const float* bk  = (const float*)d_in[5];
    const float* Wv  = (const float*)d_in[6];
    const float* bv  = (const float*)d_in[7];
    const float* Wo  = (const float*)d_in[8];
    const float* bo  = (const float*)d_in[9];
    const float* g0  = (const float*)d_in[10];
    const float* be0 = (const float*)d_in[11];
    const float* g1  = (const float*)d_in[12];
    const float* be1 = (const float*)d_in[13];
    float* out = (float*)d_out;

    float *Qp, *Kp, *Obuf, *Xbuf, *Tbuf;
    __half* Vth;
    cudaGetSymbolAddress((void**)&Qp,   g_Qp);
    cudaGetSymbolAddress((void**)&Kp,   g_Kp);
    cudaGetSymbolAddress((void**)&Vth,  g_Vth);
    cudaGetSymbolAddress((void**)&Obuf, g_O);
    cudaGetSymbolAddress((void**)&Xbuf, g_X);
    cudaGetSymbolAddress((void**)&Tbuf, g_T);

    cudaFuncSetAttribute(gemm_proj, cudaFuncAttributeMaxDynamicSharedMemorySize, GEMM_SMEM);
    cudaFuncSetAttribute(gemm_out,  cudaFuncAttributeMaxDynamicSharedMemorySize, GEMM_SMEM);
    cudaFuncSetAttribute(attn_fa,   cudaFuncAttributeMaxDynamicSharedMemorySize, ATT_SMEM);

    PArgs pa;
    pa.A[0] = Q;  pa.A[1] = K;  pa.A[2] = K;
    pa.W[0] = Wq; pa.W[1] = Wk; pa.W[2] = Wv;
    pa.b[0] = bq; pa.b[1] = bk; pa.b[2] = bv;
    pa.C[0] = Qp; pa.C[1] = Kp; pa.C[2] = Vth;

    gemm_proj<<<dim3(DV / 128, NROWS / 128, 3), 256, GEMM_SMEM>>>(pa);

    dim3 adim(8, 8, 8);                 // (q-tiles of 128, heads, batch)
    attn_fa<<<adim, 256, ATT_SMEM>>>(Qp, Kp, Vth, Obuf);

    ln512_kernel<<<NROWS, 128>>>(Obuf, g0, be0, Xbuf, 1);
    gemm_out<<<dim3(DV / 128, NROWS / 128), 256, GEMM_SMEM>>>(Xbuf, Wo, bo, Tbuf);
    ln512_kernel<<<NROWS, 128>>>(Tbuf, g1, be1, out, 0);
}

// round 13
// speedup vs baseline: 1.7183x; 1.1094x over previous
#include <cuda_runtime.h>
#include <cuda_fp16.h>
#include <math.h>
#include <stdint.h>

// ---------------- scratch ----------------
#define NROWS 8192
#define DV    512
__device__ float  g_Qp [NROWS * DV];
__device__ __half g_Kph[NROWS * DV];   // K projected, half, [row][512]
__device__ __half g_Vth[NROWS * DV];   // V projected, half, transposed: [b][h][d(64)][key(1024)]
__device__ float  g_O  [NROWS * DV];
__device__ float  g_X  [NROWS * DV];
__device__ float  g_T  [NROWS * DV];

// ---------------- helpers ----------------
__device__ __forceinline__ unsigned f2tf(float x) {
    unsigned r; asm("cvt.rna.tf32.f32 %0, %1;" : "=r"(r) : "f"(x)); return r;
}
__device__ __forceinline__ float round_tf(float x) { return __uint_as_float(f2tf(x)); }
__device__ __forceinline__ unsigned packh2(float lo, float hi) {
    __half2 h = __floats2half2_rn(lo, hi);
    return *reinterpret_cast<unsigned*>(&h);
}
__device__ __forceinline__ void mma8(float* d, const unsigned* a, const unsigned* b) {
    asm volatile(
        "mma.sync.aligned.m16n8k8.row.col.f32.tf32.tf32.f32 "
        "{%0,%1,%2,%3},{%4,%5,%6,%7},{%8,%9},{%0,%1,%2,%3};"
        : "+f"(d[0]), "+f"(d[1]), "+f"(d[2]), "+f"(d[3])
        : "r"(a[0]), "r"(a[1]), "r"(a[2]), "r"(a[3]), "r"(b[0]), "r"(b[1]));
}
__device__ __forceinline__ void mmah16(float* d, const unsigned* a, const unsigned* b) {
    asm volatile(
        "mma.sync.aligned.m16n8k16.row.col.f32.f16.f16.f32 "
        "{%0,%1,%2,%3},{%4,%5,%6,%7},{%8,%9},{%0,%1,%2,%3};"
        : "+f"(d[0]), "+f"(d[1]), "+f"(d[2]), "+f"(d[3])
        : "r"(a[0]), "r"(a[1]), "r"(a[2]), "r"(a[3]), "r"(b[0]), "r"(b[1]));
}
__device__ __forceinline__ void ldsm4(unsigned& r0, unsigned& r1, unsigned& r2, unsigned& r3,
                                      uint32_t addr) {
    asm volatile("ldmatrix.sync.aligned.m8n8.x4.shared.b16 {%0,%1,%2,%3}, [%4];"
                 : "=r"(r0), "=r"(r1), "=r"(r2), "=r"(r3) : "r"(addr));
}
__device__ __forceinline__ void cpa16(uint32_t s, const void* g) {
    asm volatile("cp.async.cg.shared.global [%0], [%1], 16;" :: "r"(s), "l"(g));
}
#define CPA_COMMIT() asm volatile("cp.async.commit_group;")
#define CPA_WAIT(n)  asm volatile("cp.async.wait_group %0;" :: "n"(n))

// ---------------- tf32 GEMM core: 128x128 tile, BK=32, 3-stage, ONE sync/iter ----------------
// mode 0: rna-rounded f32 store; 1: relu+residual(A) f32; 2: half transposed (Vt);
// 3: half store [row][512].
#define GP 36
#define GSTG (2 * 128 * GP)
#define GEMM_SMEM (3 * GSTG * 4)     // 110592 B -> 2 CTAs/SM

__device__ __forceinline__ void gemm_core(const float* __restrict__ A,
                                          const float* __restrict__ W,
                                          const float* __restrict__ bias,
                                          void* Cv, int mode, float* gsm)
{
    const int tid  = threadIdx.x;
    const int lane = tid & 31;
    const int warp = tid >> 5;
    const int wm = warp & 3;
    const int wn = warp >> 2;
    const int bm = blockIdx.y * 128;
    const int bn = blockIdx.x * 128;
    const int g4 = lane >> 2;
    const int t4 = lane & 3;
    const int i8 = lane & 7;
    const int K = 512, N = 512;

    const uint32_t gsu = (uint32_t)__cvta_generic_to_shared(gsm);
    const uint32_t obA = (uint32_t)(((wm * 32 + ((lane >> 3) & 1) * 8 + i8) * GP
                                     + (lane >> 4) * 4) * 4);
    const uint32_t obB = (uint32_t)((128 * GP + (wn * 64 + (lane >> 4) * 8 + i8) * GP
                                     + ((lane >> 3) & 1) * 4) * 4);

    float acc[2][8][4];
#pragma unroll
    for (int mi = 0; mi < 2; mi++)
#pragma unroll
        for (int ni = 0; ni < 8; ni++)
#pragma unroll
            for (int j = 0; j < 4; j++) acc[mi][ni][j] = 0.f;

    auto issue = [&](int it) {
        float* Adst = gsm + (it % 3) * GSTG;
        float* Bdst = Adst + 128 * GP;
        const int k0 = it * 32;
#pragma unroll
        for (int i = 0; i < 4; i++) {
            const int cid = i * 256 + tid;
            const int row = cid >> 3;
            const int c4  = (cid & 7) * 4;
            cpa16((uint32_t)__cvta_generic_to_shared(Adst + row * GP + c4),
                  &A[(size_t)(bm + row) * K + k0 + c4]);
        }
#pragma unroll
        for (int i = 0; i < 4; i++) {
            const int cid = i * 256 + tid;
            const int row = cid >> 3;
            const int c4  = (cid & 7) * 4;
            cpa16((uint32_t)__cvta_generic_to_shared(Bdst + row * GP + c4),
                  &W[(size_t)(bn + row) * K + k0 + c4]);
        }
    };

    const int NIT = 16;
    issue(0); CPA_COMMIT();
    issue(1); CPA_COMMIT();

    for (int it = 0; it < NIT; it++) {
        CPA_WAIT(1);
        __syncthreads();

        const uint32_t sb = gsu + (uint32_t)((it % 3) * GSTG * 4);
#pragma unroll
        for (int ks = 0; ks < 4; ks++) {
            unsigned af[2][4];
#pragma unroll
            for (int mi = 0; mi < 2; mi++)
                ldsm4(af[mi][0], af[mi][1], af[mi][2], af[mi][3],
                      sb + obA + (uint32_t)((mi * 16 * GP + ks * 8) * 4));
#pragma unroll
            for (int n2 = 0; n2 < 4; n2++) {
                unsigned b0, b1, b2, b3;
                ldsm4(b0, b1, b2, b3, sb + obB + (uint32_t)((n2 * 16 * GP + ks * 8) * 4));
                unsigned be[2] = {b0, b1}, bo_[2] = {b2, b3};
                mma8(acc[0][n2 * 2],     af[0], be);
                mma8(acc[1][n2 * 2],     af[1], be);
                mma8(acc[0][n2 * 2 + 1], af[0], bo_);
                mma8(acc[1][n2 * 2 + 1], af[1], bo_);
            }
        }

        if (it + 2 < NIT) issue(it + 2);
        CPA_COMMIT();   // empty groups in the tail keep wait-depth semantics constant
    }

#pragma unroll
    for (int mi = 0; mi < 2; mi++) {
#pragma unroll
        for (int ni = 0; ni < 8; ni++) {
            const int row = bm + wm * 32 + mi * 16 + g4;
            const int col = bn + wn * 64 + ni * 8 + 2 * t4;
            const float b0 = bias[col], b1 = bias[col + 1];
            float v00 = acc[mi][ni][0] + b0, v01 = acc[mi][ni][1] + b1;
            float v10 = acc[mi][ni][2] + b0, v11 = acc[mi][ni][3] + b1;
            if (mode == 2) {
                const int b_ = row >> 10, key = row & 1023;
                const int h_ = col >> 6, d_ = col & 63;
                __half* base = (__half*)Cv + (((size_t)(b_ * 8 + h_) * 64 + d_) << 10);
                base[key]            = __float2half(v00);
                base[1024 + key]     = __float2half(v01);
                base[key + 8]        = __float2half(v10);
                base[1024 + key + 8] = __float2half(v11);
            } else if (mode == 3) {
                __half* C = (__half*)Cv;
                *(__half2*)&C[(size_t)row * N + col]       = __floats2half2_rn(v00, v01);
                *(__half2*)&C[(size_t)(row + 8) * N + col] = __floats2half2_rn(v10, v11);
            } else {
                if (mode == 1) {
                    v00 = fmaxf(v00, 0.f) + A[(size_t)row * K + col];
                    v01 = fmaxf(v01, 0.f) + A[(size_t)row * K + col + 1];
                    v10 = fmaxf(v10, 0.f) + A[(size_t)(row + 8) * K + col];
                    v11 = fmaxf(v11, 0.f) + A[(size_t)(row + 8) * K + col + 1];
                } else {
                    v00 = round_tf(v00); v01 = round_tf(v01);
                    v10 = round_tf(v10); v11 = round_tf(v11);
                }
                float* C = (float*)Cv;
                *(float2*)&C[(size_t)row * N + col]       = make_float2(v00, v01);
                *(float2*)&C[(size_t)(row + 8) * N + col] = make_float2(v10, v11);
            }
        }
    }
}

struct PArgs {
    const float* A[3]; const float* W[3]; const float* b[3]; void* C[3]; int mode[3];
};

__global__ __launch_bounds__(256) void gemm_proj(PArgs pa) {
    extern __shared__ float gsm[];
    const int z = blockIdx.z;
    gemm_core(pa.A[z], pa.W[z], pa.b[z], pa.C[z], pa.mode[z], gsm);
}
__global__ __launch_bounds__(256) void gemm_out(const float* __restrict__ A,
                                                const float* __restrict__ W,
                                                const float* __restrict__ b, float* C) {
    extern __shared__ float gsm[];
    gemm_core(A, W, b, C, 1, gsm);
}

// ---------------- flash attention: f16 S + f16 PV, 4-stage cp.async, ONE sync/iter ----------------
// 256 threads = 8 warps; block = (128 q-rows, head, batch); warp owns 16 q rows.
#define KH 72    // tile stride in halves (144 B: 16B-aligned, bank-quad distinct — proven for V since R7)
#define ATT_SMEM (4 * 2 * 64 * KH * 2)   // 73728 B

__global__ __launch_bounds__(256, 2)
void attn_fa(const float* __restrict__ Qp, const __half* __restrict__ Kph,
             const __half* __restrict__ Vth, float* __restrict__ O)
{
    extern __shared__ __align__(16) __half hsm[];
    __half* Kst = hsm;                       // 4 stages x [64 keys][KH]
    __half* Vst = hsm + 4 * 64 * KH;         // 4 stages x [64 d][KH]

    const int tid  = threadIdx.x;
    const int lane = tid & 31;
    const int warp = tid >> 5;
    const int g4 = lane >> 2;
    const int t4 = lane & 3;
    const int i8 = lane & 7;

    const int qt = blockIdx.x, h = blockIdx.y, b = blockIdx.z;
    const int q0 = qt * 128;
    const size_t gbase  = ((size_t)b * 1024) * 512 + (size_t)h * 64;
    const size_t vtbase = ((size_t)(b * 8 + h)) << 16;
    const float scale = 0.044194173824159216f;  // 1/sqrt(512)

    // f16 B-fragment lane address (both K and V tiles share layout/stride)
    const uint32_t obB = (uint32_t)(((((lane >> 4) & 1) * 8 + i8) * KH
                                     + ((lane >> 3) & 1) * 8) * 2);
    const uint32_t ku0 = (uint32_t)__cvta_generic_to_shared(Kst);
    const uint32_t vu0 = (uint32_t)__cvta_generic_to_shared(Vst);

    auto issue = [&](int kt) {
        const int st = kt & 3;
        __half* kd = Kst + st * 64 * KH;
        __half* vd = Vst + st * 64 * KH;
#pragma unroll
        for (int i = 0; i < 2; i++) {   // K: 64 keys x 64 halves
            const int cid = i * 256 + tid;
            const int row = cid >> 3;
            const int c8  = (cid & 7) * 8;
            cpa16((uint32_t)__cvta_generic_to_shared(kd + row * KH + c8),
                  Kph + gbase + (size_t)(kt * 64 + row) * 512 + c8);
        }
#pragma unroll
        for (int i = 0; i < 2; i++) {   // V: 64 d x 64 keys
            const int cid = i * 256 + tid;
            const int row = cid >> 3;
            const int c8  = (cid & 7) * 8;
            cpa16((uint32_t)__cvta_generic_to_shared(vd + row * KH + c8),
                  Vth + vtbase + (size_t)row * 1024 + kt * 64 + c8);
        }
    };

    // Q fragments: half-packed from fp32 Qp, pre-scaled, register-resident
    const int qr = q0 + warp * 16 + g4;
    const float* Qrow0 = Qp + gbase + (size_t)qr * 512;
    const float* Qrow1 = Qrow0 + (size_t)8 * 512;
    unsigned aq[4][4];
#pragma unroll
    for (int ks = 0; ks < 4; ks++) {
        const int c = ks * 16 + 2 * t4;
        aq[ks][0] = packh2(Qrow0[c] * scale,     Qrow0[c + 1] * scale);
        aq[ks][1] = packh2(Qrow1[c] * scale,     Qrow1[c + 1] * scale);
        aq[ks][2] = packh2(Qrow0[c + 8] * scale, Qrow0[c + 9] * scale);
        aq[ks][3] = packh2(Qrow1[c + 8] * scale, Qrow1[c + 9] * scale);
    }

    float l0 = 0.f, l1 = 0.f;
    float o[8][4];
#pragma unroll
    for (int ni = 0; ni < 8; ni++)
#pragma unroll
        for (int j = 0; j < 4; j++) o[ni][j] = 0.f;

    issue(0); CPA_COMMIT();
    issue(1); CPA_COMMIT();
    issue(2); CPA_COMMIT();

    for (int kt = 0; kt < 16; kt++) {
        CPA_WAIT(2);
        __syncthreads();

        const uint32_t ku = ku0 + (uint32_t)((kt & 3) * 64 * KH * 2);
        const uint32_t vu = vu0 + (uint32_t)((kt & 3) * 64 * KH * 2);

        // S = Q @ K^T, f16 m16n8k16 (16 ldsm + 32 mma per warp-tile)
        float s[8][4];
#pragma unroll
        for (int ni = 0; ni < 8; ni++)
#pragma unroll
            for (int j = 0; j < 4; j++) s[ni][j] = 0.f;

#pragma unroll
        for (int ks = 0; ks < 4; ks++) {
#pragma unroll
            for (int n2 = 0; n2 < 4; n2++) {
                unsigned b0, b1, b2, b3;
                ldsm4(b0, b1, b2, b3, ku + obB + (uint32_t)((n2 * 16 * KH + ks * 16) * 2));
                unsigned blo[2] = {b0, b1}, bhi[2] = {b2, b3};
                mmah16(s[n2 * 2],     aq[ks], blo);
                mmah16(s[n2 * 2 + 1], aq[ks], bhi);
            }
        }

        // softmax, no max subtraction (scores bounded; clamp for safety);
        // l partial per thread (its 16 keys), reduced across t4 lanes after the loop.
#pragma unroll
        for (int ni = 0; ni < 8; ni++) {
            s[ni][0] = __expf(fminf(s[ni][0], 60.f));
            s[ni][1] = __expf(fminf(s[ni][1], 60.f));
            s[ni][2] = __expf(fminf(s[ni][2], 60.f));
            s[ni][3] = __expf(fminf(s[ni][3], 60.f));
            l0 += s[ni][0] + s[ni][1];
            l1 += s[ni][2] + s[ni][3];
        }

        // O += P @ V : P packed f32->f16 in registers (C-frag == f16 A-frag)
#pragma unroll
        for (int c = 0; c < 4; c++) {
            unsigned ap[4];
            ap[0] = packh2(s[2 * c][0],     s[2 * c][1]);
            ap[1] = packh2(s[2 * c][2],     s[2 * c][3]);
            ap[2] = packh2(s[2 * c + 1][0], s[2 * c + 1][1]);
            ap[3] = packh2(s[2 * c + 1][2], s[2 * c + 1][3]);
#pragma unroll
            for (int n2 = 0; n2 < 4; n2++) {
                unsigned b0, b1, b2, b3;
                ldsm4(b0, b1, b2, b3, vu + obB + (uint32_t)((n2 * 16 * KH + c * 16) * 2));
                unsigned blo[2] = {b0, b1}, bhi[2] = {b2, b3};
                mmah16(o[n2 * 2],     ap, blo);
                mmah16(o[n2 * 2 + 1], ap, bhi);
            }
        }

        if (kt + 3 < 16) issue(kt + 3);
        CPA_COMMIT();   // empty groups in the tail keep wait-depth semantics constant
    }

    // reduce softmax denominators across the 4 t4-lanes (full 1024-key sums)
    l0 += __shfl_xor_sync(0xffffffffu, l0, 1);
    l0 += __shfl_xor_sync(0xffffffffu, l0, 2);
    l1 += __shfl_xor_sync(0xffffffffu, l1, 1);
    l1 += __shfl_xor_sync(0xffffffffu, l1, 2);

    // epilogue: normalize + Q residual
    const float inv0 = 1.f / l0, inv1 = 1.f / l1;
    float* Ob = O + gbase + (size_t)qr * 512;
#pragma unroll
    for (int ni = 0; ni < 8; ni++) {
        const int col = ni * 8 + 2 * t4;
        float2 r0 = make_float2(o[ni][0] * inv0 + Qrow0[col],
                                o[ni][1] * inv0 + Qrow0[col + 1]);
        float2 r1 = make_float2(o[ni][2] * inv1 + Qrow1[col],
                                o[ni][3] * inv1 + Qrow1[col + 1]);
        *(float2*)&Ob[col]                   = r0;
        *(float2*)&Ob[(size_t)8 * 512 + col] = r1;
    }
}

// ---------------- layernorm over 512 features ----------------
__global__ __launch_bounds__(128)
void ln512_kernel(const float* __restrict__ X, const float* __restrict__ g,
                  const float* __restrict__ beta, float* __restrict__ Y, int roundOut)
{
    const int row = blockIdx.x;
    const int tid = threadIdx.x;
    const int lane = tid & 31;
    const int wid = tid >> 5;

    float4 v = *(const float4*)&X[(size_t)row * 512 + tid * 4];
    float s  = v.x + v.y + v.z + v.w;
    float sq = v.x * v.x + v.y * v.y + v.z * v.z + v.w * v.w;
#pragma unroll
    for (int o = 16; o; o >>= 1) {
        s  += __shfl_xor_sync(0xffffffffu, s, o);
        sq += __shfl_xor_sync(0xffffffffu, sq, o);
    }
    __shared__ float ws[4], wq[4];
    if (lane == 0) { ws[wid] = s; wq[wid] = sq; }
    __syncthreads();
    float ts = ws[0] + ws[1] + ws[2] + ws[3];
    float tq = wq[0] + wq[1] + wq[2] + wq[3];
    const float mean = ts * (1.f / 512.f);
    const float var  = tq * (1.f / 512.f) - mean * mean;
    const float rstd = rsqrtf(var + 1e-5f);

    float4 gv = *(const float4*)&g[tid * 4];
    float4 bv = *(const float4*)&beta[tid * 4];
    float4 o;
    o.x = (v.x - mean) * rstd * gv.x + bv.x;
    o.y = (v.y - mean) * rstd * gv.y + bv.y;
    o.z = (v.z - mean) * rstd * gv.z + bv.z;
    o.w = (v.w - mean) * rstd * gv.w + bv.w;
    if (roundOut) {
        o.x = round_tf(o.x); o.y = round_tf(o.y);
        o.z = round_tf(o.z); o.w = round_tf(o.w);
    }
    *(float4*)&Y[(size_t)row * 512 + tid * 4] = o;
}

// ---------------- launch ----------------
extern "C" void kernel_launch(void* const* d_in, const int* in_sizes, int n_in,
                              void* d_out, int out_size)
{
    const float* Q   = (const float*)d_in[0];
    const float* K   = (const float*)d_in[1];
    const float* Wq  = (const float*)d_in[2];
    const float* bq  = (const float*)d_in[3];
    const float* Wk  = (const float*)d_in[4];
    const float* bk  = (const float*)d_in[5];
    const float* Wv  = (const float*)d_in[6];
    const float* bv  = (const float*)d_in[7];
    const float* Wo  = (const float*)d_in[8];
    const float* bo  = (const float*)d_in[9];
    const float* g0  = (const float*)d_in[10];
    const float* be0 = (const float*)d_in[11];
    const float* g1  = (const float*)d_in[12];
    const float* be1 = (const float*)d_in[13];
    float* out = (float*)d_out;

    float *Qp, *Obuf, *Xbuf, *Tbuf;
    __half *Kph, *Vth;
    cudaGetSymbolAddress((void**)&Qp,   g_Qp);
    cudaGetSymbolAddress((void**)&Kph,  g_Kph);
    cudaGetSymbolAddress((void**)&Vth,  g_Vth);
    cudaGetSymbolAddress((void**)&Obuf, g_O);
    cudaGetSymbolAddress((void**)&Xbuf, g_X);
    cudaGetSymbolAddress((void**)&Tbuf, g_T);

    cudaFuncSetAttribute(gemm_proj, cudaFuncAttributeMaxDynamicSharedMemorySize, GEMM_SMEM);
    cudaFuncSetAttribute(gemm_out,  cudaFuncAttributeMaxDynamicSharedMemorySize, GEMM_SMEM);
    cudaFuncSetAttribute(attn_fa,   cudaFuncAttributeMaxDynamicSharedMemorySize, ATT_SMEM);

    PArgs pa;
    pa.A[0] = Q;  pa.A[1] = K;  pa.A[2] = K;
    pa.W[0] = Wq; pa.W[1] = Wk; pa.W[2] = Wv;
    pa.b[0] = bq; pa.b[1] = bk; pa.b[2] = bv;
    pa.C[0] = Qp; pa.C[1] = Kph; pa.C[2] = Vth;
    pa.mode[0] = 0; pa.mode[1] = 3; pa.mode[2] = 2;

    gemm_proj<<<dim3(DV / 128, NROWS / 128, 3), 256, GEMM_SMEM>>>(pa);

    dim3 adim(8, 8, 8);                 // (q-tiles of 128, heads, batch)
    attn_fa<<<adim, 256, ATT_SMEM>>>(Qp, Kph, Vth, Obuf);

    ln512_kernel<<<NROWS, 128>>>(Obuf, g0, be0, Xbuf, 1);
    gemm_out<<<dim3(DV / 128, NROWS / 128), 256, GEMM_SMEM>>>(Xbuf, Wo, bo, Tbuf);
    ln512_kernel<<<NROWS, 128>>>(Tbuf, g1, be1, out, 0);
}

// round 14
// speedup vs baseline: 1.7991x; 1.0470x over previous
#include <cuda_runtime.h>
#include <cuda_fp16.h>
#include <math.h>
#include <stdint.h>

// ---------------- scratch ----------------
#define NROWS 8192
#define DV    512
__device__ float  g_Qp [NROWS * DV];
__device__ __half g_Kph[NROWS * DV];   // K projected, half, [row][512]
__device__ __half g_Vth[NROWS * DV];   // V projected, half, transposed: [b][h][d(64)][key(1024)]
__device__ float  g_O  [NROWS * DV];
__device__ float  g_X  [NROWS * DV];   // LN0 output, fp32 (residual)
__device__ __half g_Xh [NROWS * DV];   // LN0 output, half (GEMM operand)
__device__ float  g_T  [NROWS * DV];
__device__ __half g_Woh[DV * DV];      // Wo in half

// ---------------- helpers ----------------
__device__ __forceinline__ unsigned f2tf(float x) {
    unsigned r; asm("cvt.rna.tf32.f32 %0, %1;" : "=r"(r) : "f"(x)); return r;
}
__device__ __forceinline__ float round_tf(float x) { return __uint_as_float(f2tf(x)); }
__device__ __forceinline__ unsigned packh2(float lo, float hi) {
    __half2 h = __floats2half2_rn(lo, hi);
    return *reinterpret_cast<unsigned*>(&h);
}
__device__ __forceinline__ void mma8(float* d, const unsigned* a, const unsigned* b) {
    asm volatile(
        "mma.sync.aligned.m16n8k8.row.col.f32.tf32.tf32.f32 "
        "{%0,%1,%2,%3},{%4,%5,%6,%7},{%8,%9},{%0,%1,%2,%3};"
        : "+f"(d[0]), "+f"(d[1]), "+f"(d[2]), "+f"(d[3])
        : "r"(a[0]), "r"(a[1]), "r"(a[2]), "r"(a[3]), "r"(b[0]), "r"(b[1]));
}
__device__ __forceinline__ void mmah16(float* d, const unsigned* a, const unsigned* b) {
    asm volatile(
        "mma.sync.aligned.m16n8k16.row.col.f32.f16.f16.f32 "
        "{%0,%1,%2,%3},{%4,%5,%6,%7},{%8,%9},{%0,%1,%2,%3};"
        : "+f"(d[0]), "+f"(d[1]), "+f"(d[2]), "+f"(d[3])
        : "r"(a[0]), "r"(a[1]), "r"(a[2]), "r"(a[3]), "r"(b[0]), "r"(b[1]));
}
__device__ __forceinline__ void ldsm4(unsigned& r0, unsigned& r1, unsigned& r2, unsigned& r3,
                                      uint32_t addr) {
    asm volatile("ldmatrix.sync.aligned.m8n8.x4.shared.b16 {%0,%1,%2,%3}, [%4];"
                 : "=r"(r0), "=r"(r1), "=r"(r2), "=r"(r3) : "r"(addr));
}
__device__ __forceinline__ void cpa16(uint32_t s, const void* g) {
    asm volatile("cp.async.cg.shared.global [%0], [%1], 16;" :: "r"(s), "l"(g));
}
#define CPA_COMMIT() asm volatile("cp.async.commit_group;")
#define CPA_WAIT(n)  asm volatile("cp.async.wait_group %0;" :: "n"(n))

// ---------------- Wo -> half convert ----------------
__global__ __launch_bounds__(256) void convW(const float* __restrict__ W, __half* __restrict__ Wh) {
    const int i = (blockIdx.x * 256 + threadIdx.x) * 8;
    const float4 f0 = *(const float4*)(W + i);
    const float4 f1 = *(const float4*)(W + i + 4);
    __half2 h[4];
    h[0] = __floats2half2_rn(f0.x, f0.y);
    h[1] = __floats2half2_rn(f0.z, f0.w);
    h[2] = __floats2half2_rn(f1.x, f1.y);
    h[3] = __floats2half2_rn(f1.z, f1.w);
    *(uint4*)(Wh + i) = *(uint4*)h;
}

// ---------------- tf32 GEMM core (projections): 128x128, BK=32, 3-stage, ONE sync/iter ----------------
// mode 0: rna-rounded f32 store; 2: half transposed (Vt); 3: half store [row][512].
#define GP 36
#define GSTG (2 * 128 * GP)
#define GEMM_SMEM (3 * GSTG * 4)     // 110592 B

__device__ __forceinline__ void gemm_core(const float* __restrict__ A,
                                          const float* __restrict__ W,
                                          const float* __restrict__ bias,
                                          void* Cv, int mode, float* gsm)
{
    const int tid  = threadIdx.x;
    const int lane = tid & 31;
    const int warp = tid >> 5;
    const int wm = warp & 3;
    const int wn = warp >> 2;
    const int bm = blockIdx.y * 128;
    const int bn = blockIdx.x * 128;
    const int g4 = lane >> 2;
    const int t4 = lane & 3;
    const int i8 = lane & 7;
    const int K = 512, N = 512;

    const uint32_t gsu = (uint32_t)__cvta_generic_to_shared(gsm);
    const uint32_t obA = (uint32_t)(((wm * 32 + ((lane >> 3) & 1) * 8 + i8) * GP
                                     + (lane >> 4) * 4) * 4);
    const uint32_t obB = (uint32_t)((128 * GP + (wn * 64 + (lane >> 4) * 8 + i8) * GP
                                     + ((lane >> 3) & 1) * 4) * 4);

    float acc[2][8][4];
#pragma unroll
    for (int mi = 0; mi < 2; mi++)
#pragma unroll
        for (int ni = 0; ni < 8; ni++)
#pragma unroll
            for (int j = 0; j < 4; j++) acc[mi][ni][j] = 0.f;

    auto issue = [&](int it) {
        float* Adst = gsm + (it % 3) * GSTG;
        float* Bdst = Adst + 128 * GP;
        const int k0 = it * 32;
#pragma unroll
        for (int i = 0; i < 4; i++) {
            const int cid = i * 256 + tid;
            const int row = cid >> 3;
            const int c4  = (cid & 7) * 4;
            cpa16((uint32_t)__cvta_generic_to_shared(Adst + row * GP + c4),
                  &A[(size_t)(bm + row) * K + k0 + c4]);
        }
#pragma unroll
        for (int i = 0; i < 4; i++) {
            const int cid = i * 256 + tid;
            const int row = cid >> 3;
            const int c4  = (cid & 7) * 4;
            cpa16((uint32_t)__cvta_generic_to_shared(Bdst + row * GP + c4),
                  &W[(size_t)(bn + row) * K + k0 + c4]);
        }
    };

    const int NIT = 16;
    issue(0); CPA_COMMIT();
    issue(1); CPA_COMMIT();

    for (int it = 0; it < NIT; it++) {
        CPA_WAIT(1);
        __syncthreads();

        const uint32_t sb = gsu + (uint32_t)((it % 3) * GSTG * 4);
#pragma unroll
        for (int ks = 0; ks < 4; ks++) {
            unsigned af[2][4];
#pragma unroll
            for (int mi = 0; mi < 2; mi++)
                ldsm4(af[mi][0], af[mi][1], af[mi][2], af[mi][3],
                      sb + obA + (uint32_t)((mi * 16 * GP + ks * 8) * 4));
#pragma unroll
            for (int n2 = 0; n2 < 4; n2++) {
                unsigned b0, b1, b2, b3;
                ldsm4(b0, b1, b2, b3, sb + obB + (uint32_t)((n2 * 16 * GP + ks * 8) * 4));
                unsigned be[2] = {b0, b1}, bo_[2] = {b2, b3};
                mma8(acc[0][n2 * 2],     af[0], be);
                mma8(acc[1][n2 * 2],     af[1], be);
                mma8(acc[0][n2 * 2 + 1], af[0], bo_);
                mma8(acc[1][n2 * 2 + 1], af[1], bo_);
            }
        }

        if (it + 2 < NIT) issue(it + 2);
        CPA_COMMIT();
    }

#pragma unroll
    for (int mi = 0; mi < 2; mi++) {
#pragma unroll
        for (int ni = 0; ni < 8; ni++) {
            const int row = bm + wm * 32 + mi * 16 + g4;
            const int col = bn + wn * 64 + ni * 8 + 2 * t4;
            const float b0 = bias[col], b1 = bias[col + 1];
            float v00 = acc[mi][ni][0] + b0, v01 = acc[mi][ni][1] + b1;
            float v10 = acc[mi][ni][2] + b0, v11 = acc[mi][ni][3] + b1;
            if (mode == 2) {
                const int b_ = row >> 10, key = row & 1023;
                const int h_ = col >> 6, d_ = col & 63;
                __half* base = (__half*)Cv + (((size_t)(b_ * 8 + h_) * 64 + d_) << 10);
                base[key]            = __float2half(v00);
                base[1024 + key]     = __float2half(v01);
                base[key + 8]        = __float2half(v10);
                base[1024 + key + 8] = __float2half(v11);
            } else if (mode == 3) {
                __half* C = (__half*)Cv;
                *(__half2*)&C[(size_t)row * N + col]       = __floats2half2_rn(v00, v01);
                *(__half2*)&C[(size_t)(row + 8) * N + col] = __floats2half2_rn(v10, v11);
            } else {
                v00 = round_tf(v00); v01 = round_tf(v01);
                v10 = round_tf(v10); v11 = round_tf(v11);
                float* C = (float*)Cv;
                *(float2*)&C[(size_t)row * N + col]       = make_float2(v00, v01);
                *(float2*)&C[(size_t)(row + 8) * N + col] = make_float2(v10, v11);
            }
        }
    }
}

struct PArgs {
    const float* A[3]; const float* W[3]; const float* b[3]; void* C[3]; int mode[3];
};

__global__ __launch_bounds__(256) void gemm_proj(PArgs pa) {
    extern __shared__ float gsm[];
    const int z = blockIdx.z;
    gemm_core(pa.A[z], pa.W[z], pa.b[z], pa.C[z], pa.mode[z], gsm);
}

// ---------------- f16 output GEMM: 128x128, BK=32, 3-stage, ONE sync/iter ----------------
// C = relu(A@W^T + bias) + resid. A, W half; resid fp32.
#define GH 40                          // halves per row (80 B: quads 0,5,2,7,4,1,6,3 -> conflict-free)
#define GSTGH (2 * 128 * GH)           // halves per stage
#define GEMMH_SMEM (3 * GSTGH * 2)     // 61440 B

__global__ __launch_bounds__(256)
void gemm_out_f16(const __half* __restrict__ A, const __half* __restrict__ W,
                  const float* __restrict__ bias, const float* __restrict__ resid,
                  float* __restrict__ C)
{
    extern __shared__ __half gsmh[];
    const int tid  = threadIdx.x;
    const int lane = tid & 31;
    const int warp = tid >> 5;
    const int wm = warp & 3;
    const int wn = warp >> 2;
    const int bm = blockIdx.y * 128;
    const int bn = blockIdx.x * 128;
    const int g4 = lane >> 2;
    const int t4 = lane & 3;
    const int i8 = lane & 7;
    const int K = 512, N = 512;

    const uint32_t gsu = (uint32_t)__cvta_generic_to_shared(gsmh);
    // fragment addressing identical to R8's correctness-verified f16 GEMM
    const uint32_t obA = (uint32_t)(((wm * 32 + ((lane >> 3) & 1) * 8 + i8) * GH
                                     + (lane >> 4) * 8) * 2);
    const uint32_t obB = (uint32_t)(128 * GH * 2
                       + ((wn * 64 + ((lane >> 4) & 1) * 8 + i8) * GH
                          + ((lane >> 3) & 1) * 8) * 2);

    float acc[2][8][4];
#pragma unroll
    for (int mi = 0; mi < 2; mi++)
#pragma unroll
        for (int ni = 0; ni < 8; ni++)
#pragma unroll
            for (int j = 0; j < 4; j++) acc[mi][ni][j] = 0.f;

    auto issue = [&](int it) {
        __half* Adst = gsmh + (it % 3) * GSTGH;
        __half* Bdst = Adst + 128 * GH;
        const int k0 = it * 32;
#pragma unroll
        for (int i = 0; i < 2; i++) {          // A: 128 rows x 32 halves = 512 16B chunks
            const int cid = i * 256 + tid;
            const int row = cid >> 2;
            const int c8  = (cid & 3) * 8;
            cpa16((uint32_t)__cvta_generic_to_shared(Adst + row * GH + c8),
                  A + (size_t)(bm + row) * K + k0 + c8);
        }
#pragma unroll
        for (int i = 0; i < 2; i++) {          // B: 128 rows x 32 halves
            const int cid = i * 256 + tid;
            const int row = cid >> 2;
            const int c8  = (cid & 3) * 8;
            cpa16((uint32_t)__cvta_generic_to_shared(Bdst + row * GH + c8),
                  W + (size_t)(bn + row) * K + k0 + c8);
        }
    };

    const int NIT = 16;
    issue(0); CPA_COMMIT();
    issue(1); CPA_COMMIT();

    for (int it = 0; it < NIT; it++) {
        CPA_WAIT(1);
        __syncthreads();

        const uint32_t sb = gsu + (uint32_t)((it % 3) * GSTGH * 2);
#pragma unroll
        for (int ks = 0; ks < 2; ks++) {       // two k-16 chunks
            unsigned af[2][4];
#pragma unroll
            for (int mi = 0; mi < 2; mi++)
                ldsm4(af[mi][0], af[mi][1], af[mi][2], af[mi][3],
                      sb + obA + (uint32_t)((mi * 16 * GH + ks * 16) * 2));
#pragma unroll
            for (int n2 = 0; n2 < 4; n2++) {
                unsigned b0, b1, b2, b3;
                ldsm4(b0, b1, b2, b3, sb + obB + (uint32_t)((n2 * 16 * GH + ks * 16) * 2));
                unsigned blo[2] = {b0, b1}, bhi[2] = {b2, b3};
                mmah16(acc[0][n2 * 2],     af[0], blo);
                mmah16(acc[1][n2 * 2],     af[1], blo);
                mmah16(acc[0][n2 * 2 + 1], af[0], bhi);
                mmah16(acc[1][n2 * 2 + 1], af[1], bhi);
            }
        }

        if (it + 2 < NIT) issue(it + 2);
        CPA_COMMIT();
    }

#pragma unroll
    for (int mi = 0; mi < 2; mi++) {
#pragma unroll
        for (int ni = 0; ni < 8; ni++) {
            const int row = bm + wm * 32 + mi * 16 + g4;
            const int col = bn + wn * 64 + ni * 8 + 2 * t4;
            const float b0 = bias[col], b1 = bias[col + 1];
            float v00 = fmaxf(acc[mi][ni][0] + b0, 0.f) + resid[(size_t)row * N + col];
            float v01 = fmaxf(acc[mi][ni][1] + b1, 0.f) + resid[(size_t)row * N + col + 1];
            float v10 = fmaxf(acc[mi][ni][2] + b0, 0.f) + resid[(size_t)(row + 8) * N + col];
            float v11 = fmaxf(acc[mi][ni][3] + b1, 0.f) + resid[(size_t)(row + 8) * N + col + 1];
            *(float2*)&C[(size_t)row * N + col]       = make_float2(v00, v01);
            *(float2*)&C[(size_t)(row + 8) * N + col] = make_float2(v10, v11);
        }
    }
}

// ---------------- flash attention: f16 S + f16 PV, 4-stage cp.async, ONE sync/iter ----------------
#define KH 72
#define ATT_SMEM (4 * 2 * 64 * KH * 2)   // 73728 B

__global__ __launch_bounds__(256, 2)
void attn_fa(const float* __restrict__ Qp, const __half* __restrict__ Kph,
             const __half* __restrict__ Vth, float* __restrict__ O)
{
    extern __shared__ __align__(16) __half hsm[];
    __half* Kst = hsm;
    __half* Vst = hsm + 4 * 64 * KH;

    const int tid  = threadIdx.x;
    const int lane = tid & 31;
    const int warp = tid >> 5;
    const int g4 = lane >> 2;
    const int t4 = lane & 3;
    const int i8 = lane & 7;

    const int qt = blockIdx.x, h = blockIdx.y, b = blockIdx.z;
    const int q0 = qt * 128;
    const size_t gbase  = ((size_t)b * 1024) * 512 + (size_t)h * 64;
    const size_t vtbase = ((size_t)(b * 8 + h)) << 16;
    const float scale = 0.044194173824159216f;

    const uint32_t obB = (uint32_t)(((((lane >> 4) & 1) * 8 + i8) * KH
                                     + ((lane >> 3) & 1) * 8) * 2);
    const uint32_t ku0 = (uint32_t)__cvta_generic_to_shared(Kst);
    const uint32_t vu0 = (uint32_t)__cvta_generic_to_shared(Vst);

    auto issue = [&](int kt) {
        const int st = kt & 3;
        __half* kd = Kst + st * 64 * KH;
        __half* vd = Vst + st * 64 * KH;
#pragma unroll
        for (int i = 0; i < 2; i++) {
            const int cid = i * 256 + tid;
            const int row = cid >> 3;
            const int c8  = (cid & 7) * 8;
            cpa16((uint32_t)__cvta_generic_to_shared(kd + row * KH + c8),
                  Kph + gbase + (size_t)(kt * 64 + row) * 512 + c8);
        }
#pragma unroll
        for (int i = 0; i < 2; i++) {
            const int cid = i * 256 + tid;
            const int row = cid >> 3;
            const int c8  = (cid & 7) * 8;
            cpa16((uint32_t)__cvta_generic_to_shared(vd + row * KH + c8),
                  Vth + vtbase + (size_t)row * 1024 + kt * 64 + c8);
        }
    };

    const int qr = q0 + warp * 16 + g4;
    const float* Qrow0 = Qp + gbase + (size_t)qr * 512;
    const float* Qrow1 = Qrow0 + (size_t)8 * 512;
    unsigned aq[4][4];
#pragma unroll
    for (int ks = 0; ks < 4; ks++) {
        const int c = ks * 16 + 2 * t4;
        aq[ks][0] = packh2(Qrow0[c] * scale,     Qrow0[c + 1] * scale);
        aq[ks][1] = packh2(Qrow1[c] * scale,     Qrow1[c + 1] * scale);
        aq[ks][2] = packh2(Qrow0[c + 8] * scale, Qrow0[c + 9] * scale);
        aq[ks][3] = packh2(Qrow1[c + 8] * scale, Qrow1[c + 9] * scale);
    }

    float l0 = 0.f, l1 = 0.f;
    float o[8][4];
#pragma unroll
    for (int ni = 0; ni < 8; ni++)
#pragma unroll
        for (int j = 0; j < 4; j++) o[ni][j] = 0.f;

    issue(0); CPA_COMMIT();
    issue(1); CPA_COMMIT();
    issue(2); CPA_COMMIT();

    for (int kt = 0; kt < 16; kt++) {
        CPA_WAIT(2);
        __syncthreads();

        const uint32_t ku = ku0 + (uint32_t)((kt & 3) * 64 * KH * 2);
        const uint32_t vu = vu0 + (uint32_t)((kt & 3) * 64 * KH * 2);

        float s[8][4];
#pragma unroll
        for (int ni = 0; ni < 8; ni++)
#pragma unroll
            for (int j = 0; j < 4; j++) s[ni][j] = 0.f;

#pragma unroll
        for (int ks = 0; ks < 4; ks++) {
#pragma unroll
            for (int n2 = 0; n2 < 4; n2++) {
                unsigned b0, b1, b2, b3;
                ldsm4(b0, b1, b2, b3, ku + obB + (uint32_t)((n2 * 16 * KH + ks * 16) * 2));
                unsigned blo[2] = {b0, b1}, bhi[2] = {b2, b3};
                mmah16(s[n2 * 2],     aq[ks], blo);
                mmah16(s[n2 * 2 + 1], aq[ks], bhi);
            }
        }

#pragma unroll
        for (int ni = 0; ni < 8; ni++) {
            s[ni][0] = __expf(fminf(s[ni][0], 60.f));
            s[ni][1] = __expf(fminf(s[ni][1], 60.f));
            s[ni][2] = __expf(fminf(s[ni][2], 60.f));
            s[ni][3] = __expf(fminf(s[ni][3], 60.f));
            l0 += s[ni][0] + s[ni][1];
            l1 += s[ni][2] + s[ni][3];
        }

#pragma unroll
        for (int c = 0; c < 4; c++) {
            unsigned ap[4];
            ap[0] = packh2(s[2 * c][0],     s[2 * c][1]);
            ap[1] = packh2(s[2 * c][2],     s[2 * c][3]);
            ap[2] = packh2(s[2 * c + 1][0], s[2 * c + 1][1]);
            ap[3] = packh2(s[2 * c + 1][2], s[2 * c + 1][3]);
#pragma unroll
            for (int n2 = 0; n2 < 4; n2++) {
                unsigned b0, b1, b2, b3;
                ldsm4(b0, b1, b2, b3, vu + obB + (uint32_t)((n2 * 16 * KH + c * 16) * 2));
                unsigned blo[2] = {b0, b1}, bhi[2] = {b2, b3};
                mmah16(o[n2 * 2],     ap, blo);
                mmah16(o[n2 * 2 + 1], ap, bhi);
            }
        }

        if (kt + 3 < 16) issue(kt + 3);
        CPA_COMMIT();
    }

    l0 += __shfl_xor_sync(0xffffffffu, l0, 1);
    l0 += __shfl_xor_sync(0xffffffffu, l0, 2);
    l1 += __shfl_xor_sync(0xffffffffu, l1, 1);
    l1 += __shfl_xor_sync(0xffffffffu, l1, 2);

    const float inv0 = 1.f / l0, inv1 = 1.f / l1;
    float* Ob = O + gbase + (size_t)qr * 512;
#pragma unroll
    for (int ni = 0; ni < 8; ni++) {
        const int col = ni * 8 + 2 * t4;
        float2 r0 = make_float2(o[ni][0] * inv0 + Qrow0[col],
                                o[ni][1] * inv0 + Qrow0[col + 1]);
        float2 r1 = make_float2(o[ni][2] * inv1 + Qrow1[col],
                                o[ni][3] * inv1 + Qrow1[col + 1]);
        *(float2*)&Ob[col]                   = r0;
        *(float2*)&Ob[(size_t)8 * 512 + col] = r1;
    }
}

// ---------------- layernorm, warp-per-row (8 rows/block, no smem) ----------------
__global__ __launch_bounds__(256)
void ln512_warp(const float* __restrict__ X, const float* __restrict__ g,
                const float* __restrict__ beta, float* __restrict__ Y,
                __half* __restrict__ Yh)
{
    const int row  = blockIdx.x * 8 + (threadIdx.x >> 5);
    const int lane = threadIdx.x & 31;
    const float* xr = X + (size_t)row * 512;

    float4 v[4];
    float s = 0.f, sq = 0.f;
#pragma unroll
    for (int i = 0; i < 4; i++) {
        v[i] = *(const float4*)(xr + i * 128 + lane * 4);
        s  += v[i].x + v[i].y + v[i].z + v[i].w;
        sq += v[i].x * v[i].x + v[i].y * v[i].y + v[i].z * v[i].z + v[i].w * v[i].w;
    }
#pragma unroll
    for (int o = 16; o; o >>= 1) {
        s  += __shfl_xor_sync(0xffffffffu, s, o);
        sq += __shfl_xor_sync(0xffffffffu, sq, o);
    }
    const float mean = s * (1.f / 512.f);
    const float var  = sq * (1.f / 512.f) - mean * mean;
    const float rstd = rsqrtf(var + 1e-5f);

    float* yr = Y + (size_t)row * 512;
#pragma unroll
    for (int i = 0; i < 4; i++) {
        const int c = i * 128 + lane * 4;
        float4 gv = *(const float4*)(g + c);
        float4 bv = *(const float4*)(beta + c);
        float4 o;
        o.x = (v[i].x - mean) * rstd * gv.x + bv.x;
        o.y = (v[i].y - mean) * rstd * gv.y + bv.y;
        o.z = (v[i].z - mean) * rstd * gv.z + bv.z;
        o.w = (v[i].w - mean) * rstd * gv.w + bv.w;
        *(float4*)(yr + c) = o;
        if (Yh) {
            __half2 hh[2];
            hh[0] = __floats2half2_rn(o.x, o.y);
            hh[1] = __floats2half2_rn(o.z, o.w);
            *(uint2*)(Yh + (size_t)row * 512 + c) = *(uint2*)hh;
        }
    }
}

// ---------------- launch ----------------
extern "C" void kernel_launch(void* const* d_in, const int* in_sizes, int n_in,
                              void* d_out, int out_size)
{
    const float* Q   = (const float*)d_in[0];
    const float* K   = (const float*)d_in[1];
    const float* Wq  = (const float*)d_in[2];
    const float* bq  = (const float*)d_in[3];
    const float* Wk  = (const float*)d_in[4];
    const float* bk  = (const float*)d_in[5];
    const float* Wv  = (const float*)d_in[6];
    const float* bv  = (const float*)d_in[7];
    const float* Wo  = (const float*)d_in[8];
    const float* bo  = (const float*)d_in[9];
    const float* g0  = (const float*)d_in[10];
    const float* be0 = (const float*)d_in[11];
    const float* g1  = (const float*)d_in[12];
    const float* be1 = (const float*)d_in[13];
    float* out = (float*)d_out;

    float *Qp, *Obuf, *Xbuf, *Tbuf;
    __half *Kph, *Vth, *Xh, *Woh;
    cudaGetSymbolAddress((void**)&Qp,   g_Qp);
    cudaGetSymbolAddress((void**)&Kph,  g_Kph);
    cudaGetSymbolAddress((void**)&Vth,  g_Vth);
    cudaGetSymbolAddress((void**)&Obuf, g_O);
    cudaGetSymbolAddress((void**)&Xbuf, g_X);
    cudaGetSymbolAddress((void**)&Xh,   g_Xh);
    cudaGetSymbolAddress((void**)&Tbuf, g_T);
    cudaGetSymbolAddress((void**)&Woh,  g_Woh);

    cudaFuncSetAttribute(gemm_proj,    cudaFuncAttributeMaxDynamicSharedMemorySize, GEMM_SMEM);
    cudaFuncSetAttribute(gemm_out_f16, cudaFuncAttributeMaxDynamicSharedMemorySize, GEMMH_SMEM);
    cudaFuncSetAttribute(attn_fa,      cudaFuncAttributeMaxDynamicSharedMemorySize, ATT_SMEM);

    convW<<<DV * DV / 2048, 256>>>(Wo, Woh);

    PArgs pa;
    pa.A[0] = Q;  pa.A[1] = K;  pa.A[2] = K;
    pa.W[0] = Wq; pa.W[1] = Wk; pa.W[2] = Wv;
    pa.b[0] = bq; pa.b[1] = bk; pa.b[2] = bv;
    pa.C[0] = Qp; pa.C[1] = Kph; pa.C[2] = Vth;
    pa.mode[0] = 0; pa.mode[1] = 3; pa.mode[2] = 2;

    gemm_proj<<<dim3(DV / 128, NROWS / 128, 3), 256, GEMM_SMEM>>>(pa);

    dim3 adim(8, 8, 8);
    attn_fa<<<adim, 256, ATT_SMEM>>>(Qp, Kph, Vth, Obuf);

    ln512_warp<<<NROWS / 8, 256>>>(Obuf, g0, be0, Xbuf, Xh);
    gemm_out_f16<<<dim3(DV / 128, NROWS / 128), 256, GEMMH_SMEM>>>(Xh, Woh, bo, Xbuf, Tbuf);
    ln512_warp<<<NROWS / 8, 256>>>(Tbuf, g1, be1, out, nullptr);
}

// round 15
// speedup vs baseline: 1.8610x; 1.0344x over previous
#include <cuda_runtime.h>
#include <cuda_fp16.h>
#include <math.h>
#include <stdint.h>

// ---------------- scratch ----------------
#define NROWS 8192
#define DV    512
__device__ float  g_Qp [NROWS * DV];
__device__ __half g_Kph[NROWS * DV];   // K projected, half, [row][512]
__device__ __half g_Vth[NROWS * DV];   // V projected, half, transposed: [b][h][d(64)][key(1024)]
__device__ float  g_O  [NROWS * DV];
__device__ float  g_X  [NROWS * DV];   // LN0 output, fp32 (residual)
__device__ __half g_Xh [NROWS * DV];   // LN0 output, half (GEMM operand)
__device__ float  g_T  [NROWS * DV];
__device__ __half g_Woh[DV * DV];      // Wo in half

// ---------------- helpers ----------------
__device__ __forceinline__ unsigned f2tf(float x) {
    unsigned r; asm("cvt.rna.tf32.f32 %0, %1;" : "=r"(r) : "f"(x)); return r;
}
__device__ __forceinline__ float round_tf(float x) { return __uint_as_float(f2tf(x)); }
__device__ __forceinline__ float ex2(float x) {
    float r; asm("ex2.approx.f32 %0, %1;" : "=f"(r) : "f"(x)); return r;
}
__device__ __forceinline__ unsigned packh2(float lo, float hi) {
    __half2 h = __floats2half2_rn(lo, hi);
    return *reinterpret_cast<unsigned*>(&h);
}
__device__ __forceinline__ void mma8(float* d, const unsigned* a, const unsigned* b) {
    asm volatile(
        "mma.sync.aligned.m16n8k8.row.col.f32.tf32.tf32.f32 "
        "{%0,%1,%2,%3},{%4,%5,%6,%7},{%8,%9},{%0,%1,%2,%3};"
        : "+f"(d[0]), "+f"(d[1]), "+f"(d[2]), "+f"(d[3])
        : "r"(a[0]), "r"(a[1]), "r"(a[2]), "r"(a[3]), "r"(b[0]), "r"(b[1]));
}
__device__ __forceinline__ void mmah16(float* d, const unsigned* a, const unsigned* b) {
    asm volatile(
        "mma.sync.aligned.m16n8k16.row.col.f32.f16.f16.f32 "
        "{%0,%1,%2,%3},{%4,%5,%6,%7},{%8,%9},{%0,%1,%2,%3};"
        : "+f"(d[0]), "+f"(d[1]), "+f"(d[2]), "+f"(d[3])
        : "r"(a[0]), "r"(a[1]), "r"(a[2]), "r"(a[3]), "r"(b[0]), "r"(b[1]));
}
__device__ __forceinline__ void ldsm4(unsigned& r0, unsigned& r1, unsigned& r2, unsigned& r3,
                                      uint32_t addr) {
    asm volatile("ldmatrix.sync.aligned.m8n8.x4.shared.b16 {%0,%1,%2,%3}, [%4];"
                 : "=r"(r0), "=r"(r1), "=r"(r2), "=r"(r3) : "r"(addr));
}
__device__ __forceinline__ void cpa16(uint32_t s, const void* g) {
    asm volatile("cp.async.cg.shared.global [%0], [%1], 16;" :: "r"(s), "l"(g));
}
#define CPA_COMMIT() asm volatile("cp.async.commit_group;")
#define CPA_WAIT(n)  asm volatile("cp.async.wait_group %0;" :: "n"(n))

// ---------------- Wo -> half convert ----------------
__global__ __launch_bounds__(256) void convW(const float* __restrict__ W, __half* __restrict__ Wh) {
    const int i = (blockIdx.x * 256 + threadIdx.x) * 8;
    const float4 f0 = *(const float4*)(W + i);
    const float4 f1 = *(const float4*)(W + i + 4);
    __half2 h[4];
    h[0] = __floats2half2_rn(f0.x, f0.y);
    h[1] = __floats2half2_rn(f0.z, f0.w);
    h[2] = __floats2half2_rn(f1.x, f1.y);
    h[3] = __floats2half2_rn(f1.z, f1.w);
    *(uint4*)(Wh + i) = *(uint4*)h;
}

// ---------------- tf32 GEMM core (projections): 128x128, BK=32, 3-stage, ONE sync/iter ----------------
// A-fragments hoisted: all 8 A-ldsm at top of iteration -> B-ldsm+mma stream has deep ILP.
// mode 0: rna-rounded f32 store; 2: half transposed (Vt); 3: half store [row][512].
#define GP 36
#define GSTG (2 * 128 * GP)
#define GEMM_SMEM (3 * GSTG * 4)     // 110592 B -> 2 CTAs/SM

__device__ __forceinline__ void gemm_core(const float* __restrict__ A,
                                          const float* __restrict__ W,
                                          const float* __restrict__ bias,
                                          void* Cv, int mode, float* gsm)
{
    const int tid  = threadIdx.x;
    const int lane = tid & 31;
    const int warp = tid >> 5;
    const int wm = warp & 3;
    const int wn = warp >> 2;
    const int bm = blockIdx.y * 128;
    const int bn = blockIdx.x * 128;
    const int g4 = lane >> 2;
    const int t4 = lane & 3;
    const int i8 = lane & 7;
    const int K = 512, N = 512;

    const uint32_t gsu = (uint32_t)__cvta_generic_to_shared(gsm);
    const uint32_t obA = (uint32_t)(((wm * 32 + ((lane >> 3) & 1) * 8 + i8) * GP
                                     + (lane >> 4) * 4) * 4);
    const uint32_t obB = (uint32_t)((128 * GP + (wn * 64 + (lane >> 4) * 8 + i8) * GP
                                     + ((lane >> 3) & 1) * 4) * 4);

    float acc[2][8][4];
#pragma unroll
    for (int mi = 0; mi < 2; mi++)
#pragma unroll
        for (int ni = 0; ni < 8; ni++)
#pragma unroll
            for (int j = 0; j < 4; j++) acc[mi][ni][j] = 0.f;

    auto issue = [&](int it) {
        float* Adst = gsm + (it % 3) * GSTG;
        float* Bdst = Adst + 128 * GP;
        const int k0 = it * 32;
#pragma unroll
        for (int i = 0; i < 4; i++) {
            const int cid = i * 256 + tid;
            const int row = cid >> 3;
            const int c4  = (cid & 7) * 4;
            cpa16((uint32_t)__cvta_generic_to_shared(Adst + row * GP + c4),
                  &A[(size_t)(bm + row) * K + k0 + c4]);
        }
#pragma unroll
        for (int i = 0; i < 4; i++) {
            const int cid = i * 256 + tid;
            const int row = cid >> 3;
            const int c4  = (cid & 7) * 4;
            cpa16((uint32_t)__cvta_generic_to_shared(Bdst + row * GP + c4),
                  &W[(size_t)(bn + row) * K + k0 + c4]);
        }
    };

    const int NIT = 16;
    issue(0); CPA_COMMIT();
    issue(1); CPA_COMMIT();

    for (int it = 0; it < NIT; it++) {
        CPA_WAIT(1);
        __syncthreads();

        const uint32_t sb = gsu + (uint32_t)((it % 3) * GSTG * 4);

        // hoisted A-fragments: 8 ldsm up front (32 regs)
        unsigned af[4][2][4];
#pragma unroll
        for (int ks = 0; ks < 4; ks++)
#pragma unroll
            for (int mi = 0; mi < 2; mi++)
                ldsm4(af[ks][mi][0], af[ks][mi][1], af[ks][mi][2], af[ks][mi][3],
                      sb + obA + (uint32_t)((mi * 16 * GP + ks * 8) * 4));

#pragma unroll
        for (int ks = 0; ks < 4; ks++) {
#pragma unroll
            for (int n2 = 0; n2 < 4; n2++) {
                unsigned b0, b1, b2, b3;
                ldsm4(b0, b1, b2, b3, sb + obB + (uint32_t)((n2 * 16 * GP + ks * 8) * 4));
                unsigned be[2] = {b0, b1}, bo_[2] = {b2, b3};
                mma8(acc[0][n2 * 2],     af[ks][0], be);
                mma8(acc[1][n2 * 2],     af[ks][1], be);
                mma8(acc[0][n2 * 2 + 1], af[ks][0], bo_);
                mma8(acc[1][n2 * 2 + 1], af[ks][1], bo_);
            }
        }

        if (it + 2 < NIT) issue(it + 2);
        CPA_COMMIT();
    }

#pragma unroll
    for (int mi = 0; mi < 2; mi++) {
#pragma unroll
        for (int ni = 0; ni < 8; ni++) {
            const int row = bm + wm * 32 + mi * 16 + g4;
            const int col = bn + wn * 64 + ni * 8 + 2 * t4;
            const float b0 = bias[col], b1 = bias[col + 1];
            float v00 = acc[mi][ni][0] + b0, v01 = acc[mi][ni][1] + b1;
            float v10 = acc[mi][ni][2] + b0, v11 = acc[mi][ni][3] + b1;
            if (mode == 2) {
                const int b_ = row >> 10, key = row & 1023;
                const int h_ = col >> 6, d_ = col & 63;
                __half* base = (__half*)Cv + (((size_t)(b_ * 8 + h_) * 64 + d_) << 10);
                base[key]            = __float2half(v00);
                base[1024 + key]     = __float2half(v01);
                base[key + 8]        = __float2half(v10);
                base[1024 + key + 8] = __float2half(v11);
            } else if (mode == 3) {
                __half* C = (__half*)Cv;
                *(__half2*)&C[(size_t)row * N + col]       = __floats2half2_rn(v00, v01);
                *(__half2*)&C[(size_t)(row + 8) * N + col] = __floats2half2_rn(v10, v11);
            } else {
                v00 = round_tf(v00); v01 = round_tf(v01);
                v10 = round_tf(v10); v11 = round_tf(v11);
                float* C = (float*)Cv;
                *(float2*)&C[(size_t)row * N + col]       = make_float2(v00, v01);
                *(float2*)&C[(size_t)(row + 8) * N + col] = make_float2(v10, v11);
            }
        }
    }
}

struct PArgs {
    const float* A[3]; const float* W[3]; const float* b[3]; void* C[3]; int mode[3];
};

__global__ __launch_bounds__(256, 2) void gemm_proj(PArgs pa) {
    extern __shared__ float gsm[];
    const int z = blockIdx.z;
    gemm_core(pa.A[z], pa.W[z], pa.b[z], pa.C[z], pa.mode[z], gsm);
}

// ---------------- f16 output GEMM: 128x128, BK=32, 3-stage, ONE sync/iter, hoisted A ----------------
#define GH 40
#define GSTGH (2 * 128 * GH)
#define GEMMH_SMEM (3 * GSTGH * 2)     // 61440 B

__global__ __launch_bounds__(256, 2)
void gemm_out_f16(const __half* __restrict__ A, const __half* __restrict__ W,
                  const float* __restrict__ bias, const float* __restrict__ resid,
                  float* __restrict__ C)
{
    extern __shared__ __half gsmh[];
    const int tid  = threadIdx.x;
    const int lane = tid & 31;
    const int warp = tid >> 5;
    const int wm = warp & 3;
    const int wn = warp >> 2;
    const int bm = blockIdx.y * 128;
    const int bn = blockIdx.x * 128;
    const int g4 = lane >> 2;
    const int t4 = lane & 3;
    const int i8 = lane & 7;
    const int K = 512, N = 512;

    const uint32_t gsu = (uint32_t)__cvta_generic_to_shared(gsmh);
    const uint32_t obA = (uint32_t)(((wm * 32 + ((lane >> 3) & 1) * 8 + i8) * GH
                                     + (lane >> 4) * 8) * 2);
    const uint32_t obB = (uint32_t)(128 * GH * 2
                       + ((wn * 64 + ((lane >> 4) & 1) * 8 + i8) * GH
                          + ((lane >> 3) & 1) * 8) * 2);

    float acc[2][8][4];
#pragma unroll
    for (int mi = 0; mi < 2; mi++)
#pragma unroll
        for (int ni = 0; ni < 8; ni++)
#pragma unroll
            for (int j = 0; j < 4; j++) acc[mi][ni][j] = 0.f;

    auto issue = [&](int it) {
        __half* Adst = gsmh + (it % 3) * GSTGH;
        __half* Bdst = Adst + 128 * GH;
        const int k0 = it * 32;
#pragma unroll
        for (int i = 0; i < 2; i++) {
            const int cid = i * 256 + tid;
            const int row = cid >> 2;
            const int c8  = (cid & 3) * 8;
            cpa16((uint32_t)__cvta_generic_to_shared(Adst + row * GH + c8),
                  A + (size_t)(bm + row) * K + k0 + c8);
        }
#pragma unroll
        for (int i = 0; i < 2; i++) {
            const int cid = i * 256 + tid;
            const int row = cid >> 2;
            const int c8  = (cid & 3) * 8;
            cpa16((uint32_t)__cvta_generic_to_shared(Bdst + row * GH + c8),
                  W + (size_t)(bn + row) * K + k0 + c8);
        }
    };

    const int NIT = 16;
    issue(0); CPA_COMMIT();
    issue(1); CPA_COMMIT();

    for (int it = 0; it < NIT; it++) {
        CPA_WAIT(1);
        __syncthreads();

        const uint32_t sb = gsu + (uint32_t)((it % 3) * GSTGH * 2);

        // hoisted A-fragments: 4 ldsm up front (16 regs)
        unsigned af[2][2][4];
#pragma unroll
        for (int ks = 0; ks < 2; ks++)
#pragma unroll
            for (int mi = 0; mi < 2; mi++)
                ldsm4(af[ks][mi][0], af[ks][mi][1], af[ks][mi][2], af[ks][mi][3],
                      sb + obA + (uint32_t)((mi * 16 * GH + ks * 16) * 2));

#pragma unroll
        for (int ks = 0; ks < 2; ks++) {
#pragma unroll
            for (int n2 = 0; n2 < 4; n2++) {
                unsigned b0, b1, b2, b3;
                ldsm4(b0, b1, b2, b3, sb + obB + (uint32_t)((n2 * 16 * GH + ks * 16) * 2));
                unsigned blo[2] = {b0, b1}, bhi[2] = {b2, b3};
                mmah16(acc[0][n2 * 2],     af[ks][0], blo);
                mmah16(acc[1][n2 * 2],     af[ks][1], blo);
                mmah16(acc[0][n2 * 2 + 1], af[ks][0], bhi);
                mmah16(acc[1][n2 * 2 + 1], af[ks][1], bhi);
            }
        }

        if (it + 2 < NIT) issue(it + 2);
        CPA_COMMIT();
    }

#pragma unroll
    for (int mi = 0; mi < 2; mi++) {
#pragma unroll
        for (int ni = 0; ni < 8; ni++) {
            const int row = bm + wm * 32 + mi * 16 + g4;
            const int col = bn + wn * 64 + ni * 8 + 2 * t4;
            const float b0 = bias[col], b1 = bias[col + 1];
            float v00 = fmaxf(acc[mi][ni][0] + b0, 0.f) + resid[(size_t)row * N + col];
            float v01 = fmaxf(acc[mi][ni][1] + b1, 0.f) + resid[(size_t)row * N + col + 1];
            float v10 = fmaxf(acc[mi][ni][2] + b0, 0.f) + resid[(size_t)(row + 8) * N + col];
            float v11 = fmaxf(acc[mi][ni][3] + b1, 0.f) + resid[(size_t)(row + 8) * N + col + 1];
            *(float2*)&C[(size_t)row * N + col]       = make_float2(v00, v01);
            *(float2*)&C[(size_t)(row + 8) * N + col] = make_float2(v10, v11);
        }
    }
}

// ---------------- flash attention: f16 S + f16 PV, 4-stage cp.async, ONE sync/iter ----------------
// exp2 trick: log2(e) folded into the Q scale -> softmax is a bare ex2.approx.
#define KH 72
#define ATT_SMEM (4 * 2 * 64 * KH * 2)   // 73728 B

__global__ __launch_bounds__(256, 2)
void attn_fa(const float* __restrict__ Qp, const __half* __restrict__ Kph,
             const __half* __restrict__ Vth, float* __restrict__ O)
{
    extern __shared__ __align__(16) __half hsm[];
    __half* Kst = hsm;
    __half* Vst = hsm + 4 * 64 * KH;

    const int tid  = threadIdx.x;
    const int lane = tid & 31;
    const int warp = tid >> 5;
    const int g4 = lane >> 2;
    const int t4 = lane & 3;
    const int i8 = lane & 7;

    const int qt = blockIdx.x, h = blockIdx.y, b = blockIdx.z;
    const int q0 = qt * 128;
    const size_t gbase  = ((size_t)b * 1024) * 512 + (size_t)h * 64;
    const size_t vtbase = ((size_t)(b * 8 + h)) << 16;
    // 1/sqrt(512) * log2(e): softmax exp(s) == exp2(s') with s' = q.k * this
    const float scale = 0.044194173824159216f * 1.4426950408889634f;

    const uint32_t obB = (uint32_t)(((((lane >> 4) & 1) * 8 + i8) * KH
                                     + ((lane >> 3) & 1) * 8) * 2);
    const uint32_t ku0 = (uint32_t)__cvta_generic_to_shared(Kst);
    const uint32_t vu0 = (uint32_t)__cvta_generic_to_shared(Vst);

    auto issue = [&](int kt) {
        const int st = kt & 3;
        __half* kd = Kst + st * 64 * KH;
        __half* vd = Vst + st * 64 * KH;
#pragma unroll
        for (int i = 0; i < 2; i++) {
            const int cid = i * 256 + tid;
            const int row = cid >> 3;
            const int c8  = (cid & 7) * 8;
            cpa16((uint32_t)__cvta_generic_to_shared(kd + row * KH + c8),
                  Kph + gbase + (size_t)(kt * 64 + row) * 512 + c8);
        }
#pragma unroll
        for (int i = 0; i < 2; i++) {
            const int cid = i * 256 + tid;
            const int row = cid >> 3;
            const int c8  = (cid & 7) * 8;
            cpa16((uint32_t)__cvta_generic_to_shared(vd + row * KH + c8),
                  Vth + vtbase + (size_t)row * 1024 + kt * 64 + c8);
        }
    };

    const int qr = q0 + warp * 16 + g4;
    const float* Qrow0 = Qp + gbase + (size_t)qr * 512;
    const float* Qrow1 = Qrow0 + (size_t)8 * 512;
    unsigned aq[4][4];
#pragma unroll
    for (int ks = 0; ks < 4; ks++) {
        const int c = ks * 16 + 2 * t4;
        aq[ks][0] = packh2(Qrow0[c] * scale,     Qrow0[c + 1] * scale);
        aq[ks][1] = packh2(Qrow1[c] * scale,     Qrow1[c + 1] * scale);
        aq[ks][2] = packh2(Qrow0[c + 8] * scale, Qrow0[c + 9] * scale);
        aq[ks][3] = packh2(Qrow1[c + 8] * scale, Qrow1[c + 9] * scale);
    }

    float l0 = 0.f, l1 = 0.f;
    float o[8][4];
#pragma unroll
    for (int ni = 0; ni < 8; ni++)
#pragma unroll
        for (int j = 0; j < 4; j++) o[ni][j] = 0.f;

    issue(0); CPA_COMMIT();
    issue(1); CPA_COMMIT();
    issue(2); CPA_COMMIT();

    for (int kt = 0; kt < 16; kt++) {
        CPA_WAIT(2);
        __syncthreads();

        const uint32_t ku = ku0 + (uint32_t)((kt & 3) * 64 * KH * 2);
        const uint32_t vu = vu0 + (uint32_t)((kt & 3) * 64 * KH * 2);

        float s[8][4];
#pragma unroll
        for (int ni = 0; ni < 8; ni++)
#pragma unroll
            for (int j = 0; j < 4; j++) s[ni][j] = 0.f;

#pragma unroll
        for (int ks = 0; ks < 4; ks++) {
#pragma unroll
            for (int n2 = 0; n2 < 4; n2++) {
                unsigned b0, b1, b2, b3;
                ldsm4(b0, b1, b2, b3, ku + obB + (uint32_t)((n2 * 16 * KH + ks * 16) * 2));
                unsigned blo[2] = {b0, b1}, bhi[2] = {b2, b3};
                mmah16(s[n2 * 2],     aq[ks], blo);
                mmah16(s[n2 * 2 + 1], aq[ks], bhi);
            }
        }

        // softmax via raw ex2 (log2e pre-folded); no max subtraction (scores bounded; clamp).
#pragma unroll
        for (int ni = 0; ni < 8; ni++) {
            s[ni][0] = ex2(fminf(s[ni][0], 86.f));
            s[ni][1] = ex2(fminf(s[ni][1], 86.f));
            s[ni][2] = ex2(fminf(s[ni][2], 86.f));
            s[ni][3] = ex2(fminf(s[ni][3], 86.f));
            l0 += s[ni][0] + s[ni][1];
            l1 += s[ni][2] + s[ni][3];
        }

#pragma unroll
        for (int c = 0; c < 4; c++) {
            unsigned ap[4];
            ap[0] = packh2(s[2 * c][0],     s[2 * c][1]);
            ap[1] = packh2(s[2 * c][2],     s[2 * c][3]);
            ap[2] = packh2(s[2 * c + 1][0], s[2 * c + 1][1]);
            ap[3] = packh2(s[2 * c + 1][2], s[2 * c + 1][3]);
#pragma unroll
            for (int n2 = 0; n2 < 4; n2++) {
                unsigned b0, b1, b2, b3;
                ldsm4(b0, b1, b2, b3, vu + obB + (uint32_t)((n2 * 16 * KH + c * 16) * 2));
                unsigned blo[2] = {b0, b1}, bhi[2] = {b2, b3};
                mmah16(o[n2 * 2],     ap, blo);
                mmah16(o[n2 * 2 + 1], ap, bhi);
            }
        }

        if (kt + 3 < 16) issue(kt + 3);
        CPA_COMMIT();
    }

    l0 += __shfl_xor_sync(0xffffffffu, l0, 1);
    l0 += __shfl_xor_sync(0xffffffffu, l0, 2);
    l1 += __shfl_xor_sync(0xffffffffu, l1, 1);
    l1 += __shfl_xor_sync(0xffffffffu, l1, 2);

    const float inv0 = 1.f / l0, inv1 = 1.f / l1;
    float* Ob = O + gbase + (size_t)qr * 512;
#pragma unroll
    for (int ni = 0; ni < 8; ni++) {
        const int col = ni * 8 + 2 * t4;
        float2 r0 = make_float2(o[ni][0] * inv0 + Qrow0[col],
                                o[ni][1] * inv0 + Qrow0[col + 1]);
        float2 r1 = make_float2(o[ni][2] * inv1 + Qrow1[col],
                                o[ni][3] * inv1 + Qrow1[col + 1]);
        *(float2*)&Ob[col]                   = r0;
        *(float2*)&Ob[(size_t)8 * 512 + col] = r1;
    }
}

// ---------------- layernorm, warp-per-row (8 rows/block, no smem) ----------------
__global__ __launch_bounds__(256)
void ln512_warp(const float* __restrict__ X, const float* __restrict__ g,
                const float* __restrict__ beta, float* __restrict__ Y,
                __half* __restrict__ Yh)
{
    const int row  = blockIdx.x * 8 + (threadIdx.x >> 5);
    const int lane = threadIdx.x & 31;
    const float* xr = X + (size_t)row * 512;

    float4 v[4];
    float s = 0.f, sq = 0.f;
#pragma unroll
    for (int i = 0; i < 4; i++) {
        v[i] = *(const float4*)(xr + i * 128 + lane * 4);
        s  += v[i].x + v[i].y + v[i].z + v[i].w;
        sq += v[i].x * v[i].x + v[i].y * v[i].y + v[i].z * v[i].z + v[i].w * v[i].w;
    }
#pragma unroll
    for (int o = 16; o; o >>= 1) {
        s  += __shfl_xor_sync(0xffffffffu, s, o);
        sq += __shfl_xor_sync(0xffffffffu, sq, o);
    }
    const float mean = s * (1.f / 512.f);
    const float var  = sq * (1.f / 512.f) - mean * mean;
    const float rstd = rsqrtf(var + 1e-5f);

    float* yr = Y + (size_t)row * 512;
#pragma unroll
    for (int i = 0; i < 4; i++) {
        const int c = i * 128 + lane * 4;
        float4 gv = *(const float4*)(g + c);
        float4 bv = *(const float4*)(beta + c);
        float4 o;
        o.x = (v[i].x - mean) * rstd * gv.x + bv.x;
        o.y = (v[i].y - mean) * rstd * gv.y + bv.y;
        o.z = (v[i].z - mean) * rstd * gv.z + bv.z;
        o.w = (v[i].w - mean) * rstd * gv.w + bv.w;
        *(float4*)(yr + c) = o;
        if (Yh) {
            __half2 hh[2];
            hh[0] = __floats2half2_rn(o.x, o.y);
            hh[1] = __floats2half2_rn(o.z, o.w);
            *(uint2*)(Yh + (size_t)row * 512 + c) = *(uint2*)hh;
        }
    }
}

// ---------------- launch ----------------
extern "C" void kernel_launch(void* const* d_in, const int* in_sizes, int n_in,
                              void* d_out, int out_size)
{
    const float* Q   = (const float*)d_in[0];
    const float* K   = (const float*)d_in[1];
    const float* Wq  = (const float*)d_in[2];
    const float* bq  = (const float*)d_in[3];
    const float* Wk  = (const float*)d_in[4];
    const float* bk  = (const float*)d_in[5];
    const float* Wv  = (const float*)d_in[6];
    const float* bv  = (const float*)d_in[7];
    const float* Wo  = (const float*)d_in[8];
    const float* bo  = (const float*)d_in[9];
    const float* g0  = (const float*)d_in[10];
    const float* be0 = (const float*)d_in[11];
    const float* g1  = (const float*)d_in[12];
    const float* be1 = (const float*)d_in[13];
    float* out = (float*)d_out;

    float *Qp, *Obuf, *Xbuf, *Tbuf;
    __half *Kph, *Vth, *Xh, *Woh;
    cudaGetSymbolAddress((void**)&Qp,   g_Qp);
    cudaGetSymbolAddress((void**)&Kph,  g_Kph);
    cudaGetSymbolAddress((void**)&Vth,  g_Vth);
    cudaGetSymbolAddress((void**)&Obuf, g_O);
    cudaGetSymbolAddress((void**)&Xbuf, g_X);
    cudaGetSymbolAddress((void**)&Xh,   g_Xh);
    cudaGetSymbolAddress((void**)&Tbuf, g_T);
    cudaGetSymbolAddress((void**)&Woh,  g_Woh);

    cudaFuncSetAttribute(gemm_proj,    cudaFuncAttributeMaxDynamicSharedMemorySize, GEMM_SMEM);
    cudaFuncSetAttribute(gemm_out_f16, cudaFuncAttributeMaxDynamicSharedMemorySize, GEMMH_SMEM);
    cudaFuncSetAttribute(attn_fa,      cudaFuncAttributeMaxDynamicSharedMemorySize, ATT_SMEM);

    convW<<<DV * DV / 2048, 256>>>(Wo, Woh);

    PArgs pa;
    pa.A[0] = Q;  pa.A[1] = K;  pa.A[2] = K;
    pa.W[0] = Wq; pa.W[1] = Wk; pa.W[2] = Wv;
    pa.b[0] = bq; pa.b[1] = bk; pa.b[2] = bv;
    pa.C[0] = Qp; pa.C[1] = Kph; pa.C[2] = Vth;
    pa.mode[0] = 0; pa.mode[1] = 3; pa.mode[2] = 2;

    gemm_proj<<<dim3(DV / 128, NROWS / 128, 3), 256, GEMM_SMEM>>>(pa);

    dim3 adim(8, 8, 8);
    attn_fa<<<adim, 256, ATT_SMEM>>>(Qp, Kph, Vth, Obuf);

    ln512_warp<<<NROWS / 8, 256>>>(Obuf, g0, be0, Xbuf, Xh);
    gemm_out_f16<<<dim3(DV / 128, NROWS / 128), 256, GEMMH_SMEM>>>(Xh, Woh, bo, Xbuf, Tbuf);
    ln512_warp<<<NROWS / 8, 256>>>(Tbuf, g1, be1, out, nullptr);
}